// round 1
// baseline (speedup 1.0000x reference)
#include <cuda_runtime.h>
#include <cuda_bf16.h>
#include <cstdint>

// Problem constants
#define B_ 2
#define S_ 2048
#define D_ 768
#define H_ 12
#define DH_ 64
#define L_ 2
#define DFF_ 3072
#define MROWS (B_ * S_)   // 4096

// ---------------------------------------------------------------------------
// Scratch (static device globals — no allocation allowed)
// ---------------------------------------------------------------------------
__device__ float g_x  [MROWS * D_];
__device__ float g_q  [MROWS * D_];
__device__ float g_k  [MROWS * D_];
__device__ float g_v  [MROWS * D_];
__device__ float g_att[MROWS * D_];
__device__ float g_tmp[MROWS * D_];
__device__ float g_ff [MROWS * DFF_];

// ---------------------------------------------------------------------------
// SGEMM: C[M,N] = A[M,K] @ W[N,K]^T + bias[N]   (optional ReLU)
// BM=BN=128, BK=8, 256 threads, 8x8 per thread.
// M % 128 == 0, N % 128 == 0, K % 8 == 0 (all true here).
// ---------------------------------------------------------------------------
template <int EPI>  // 0 = bias, 1 = bias + relu
__global__ __launch_bounds__(256) void sgemm_kernel(
    const float* __restrict__ A, const float* __restrict__ W,
    const float* __restrict__ bias, float* __restrict__ C,
    int M, int N, int K)
{
    constexpr int BM = 128, BN = 128, BK = 8, TM = 8, TN = 8;
    __shared__ float As[BK][BM];
    __shared__ float Bs[BK][BN];

    const int tid = threadIdx.x;
    const int bm = blockIdx.y * BM;
    const int bn = blockIdx.x * BN;
    const int tx = (tid % 16) * TN;
    const int ty = (tid / 16) * TM;

    float acc[TM][TN];
#pragma unroll
    for (int i = 0; i < TM; i++)
#pragma unroll
        for (int j = 0; j < TN; j++) acc[i][j] = 0.f;

    // each thread loads one float4 of A and one of W per BK slab
    const int lrow = tid >> 1;           // 0..127
    const int lcol = (tid & 1) * 4;      // 0 or 4
    const float* Aptr = A + (size_t)(bm + lrow) * K + lcol;
    const float* Wptr = W + (size_t)(bn + lrow) * K + lcol;

    for (int k0 = 0; k0 < K; k0 += BK) {
        float4 av = *(const float4*)(Aptr + k0);
        float4 wv = *(const float4*)(Wptr + k0);
        As[lcol + 0][lrow] = av.x; As[lcol + 1][lrow] = av.y;
        As[lcol + 2][lrow] = av.z; As[lcol + 3][lrow] = av.w;
        Bs[lcol + 0][lrow] = wv.x; Bs[lcol + 1][lrow] = wv.y;
        Bs[lcol + 2][lrow] = wv.z; Bs[lcol + 3][lrow] = wv.w;
        __syncthreads();

#pragma unroll
        for (int kk = 0; kk < BK; kk++) {
            float4 a0 = *(const float4*)&As[kk][ty];
            float4 a1 = *(const float4*)&As[kk][ty + 4];
            float4 b0 = *(const float4*)&Bs[kk][tx];
            float4 b1 = *(const float4*)&Bs[kk][tx + 4];
            float a[TM] = {a0.x, a0.y, a0.z, a0.w, a1.x, a1.y, a1.z, a1.w};
            float b[TN] = {b0.x, b0.y, b0.z, b0.w, b1.x, b1.y, b1.z, b1.w};
#pragma unroll
            for (int i = 0; i < TM; i++)
#pragma unroll
                for (int j = 0; j < TN; j++) acc[i][j] += a[i] * b[j];
        }
        __syncthreads();
    }

#pragma unroll
    for (int i = 0; i < TM; i++) {
        const int m = bm + ty + i;
        float* crow = C + (size_t)m * N;
#pragma unroll
        for (int j = 0; j < TN; j += 4) {
            const int n = bn + tx + j;
            float4 r;
            r.x = acc[i][j + 0] + bias[n + 0];
            r.y = acc[i][j + 1] + bias[n + 1];
            r.z = acc[i][j + 2] + bias[n + 2];
            r.w = acc[i][j + 3] + bias[n + 3];
            if (EPI == 1) {
                r.x = fmaxf(r.x, 0.f); r.y = fmaxf(r.y, 0.f);
                r.z = fmaxf(r.z, 0.f); r.w = fmaxf(r.w, 0.f);
            }
            *(float4*)(crow + n) = r;
        }
    }
}

// ---------------------------------------------------------------------------
// Banded flash attention.
// One block = 128 queries of one (b,h). Each thread owns one query:
// q[64] and o[64] in registers, online softmax. K/V tiles of 64 keys staged
// in shared; Ks/Vs reads are warp-broadcast (same j for all lanes).
// Band: |i - j| <= 256. Output written to (B*S, D) layout at head offset.
// ---------------------------------------------------------------------------
__global__ __launch_bounds__(128) void attn_kernel(
    const float* __restrict__ Q, const float* __restrict__ Kx,
    const float* __restrict__ Vx, float* __restrict__ O)
{
    __shared__ float Ks[64][64];
    __shared__ float Vs[64][64];

    const int b = blockIdx.z;
    const int h = blockIdx.y;
    const int q0 = blockIdx.x * 128;
    const int tid = threadIdx.x;
    const int qi = q0 + tid;

    const float scale = 0.125f;  // 64^-0.5
    float q[64];
    {
        const float* qp = Q + (size_t)(b * S_ + qi) * D_ + h * DH_;
#pragma unroll
        for (int i = 0; i < 16; i++) {
            float4 t = *(const float4*)(qp + 4 * i);
            q[4 * i + 0] = t.x * scale; q[4 * i + 1] = t.y * scale;
            q[4 * i + 2] = t.z * scale; q[4 * i + 3] = t.w * scale;
        }
    }
    float o[64];
#pragma unroll
    for (int i = 0; i < 64; i++) o[i] = 0.f;
    float mmax = -1e30f, lsum = 0.f;

    int ks0 = q0 - 256; if (ks0 < 0) ks0 = 0;
    int ke  = q0 + 128 + 256; if (ke > S_) ke = S_;

    for (int ks = ks0; ks < ke; ks += 64) {
        // stage K/V tile: 2 threads per row, 8 float4 each
        const int row = tid >> 1;
        const int c0  = (tid & 1) * 32;
        const float* kp = Kx + (size_t)(b * S_ + ks + row) * D_ + h * DH_ + c0;
        const float* vp = Vx + (size_t)(b * S_ + ks + row) * D_ + h * DH_ + c0;
#pragma unroll
        for (int i = 0; i < 8; i++) {
            *(float4*)&Ks[row][c0 + 4 * i] = *(const float4*)(kp + 4 * i);
            *(float4*)&Vs[row][c0 + 4 * i] = *(const float4*)(vp + 4 * i);
        }
        __syncthreads();

        int jlo = qi - 256 - ks; if (jlo < 0) jlo = 0;
        int jhi = qi + 256 - ks; if (jhi > 63) jhi = 63;
        for (int j = jlo; j <= jhi; j++) {
            float s = 0.f;
#pragma unroll
            for (int i2 = 0; i2 < 16; i2++) {
                float4 kv = *(const float4*)&Ks[j][4 * i2];
                s += q[4 * i2 + 0] * kv.x + q[4 * i2 + 1] * kv.y
                   + q[4 * i2 + 2] * kv.z + q[4 * i2 + 3] * kv.w;
            }
            float mn = fmaxf(mmax, s);
            float p = __expf(s - mn);
            if (mn > mmax) {
                float corr = __expf(mmax - mn);
                lsum *= corr;
#pragma unroll
                for (int i2 = 0; i2 < 64; i2++) o[i2] *= corr;
                mmax = mn;
            }
            lsum += p;
#pragma unroll
            for (int i2 = 0; i2 < 16; i2++) {
                float4 vv = *(const float4*)&Vs[j][4 * i2];
                o[4 * i2 + 0] += p * vv.x; o[4 * i2 + 1] += p * vv.y;
                o[4 * i2 + 2] += p * vv.z; o[4 * i2 + 3] += p * vv.w;
            }
        }
        __syncthreads();
    }

    const float inv = 1.f / lsum;
    float* op = O + (size_t)(b * S_ + qi) * D_ + h * DH_;
#pragma unroll
    for (int i = 0; i < 16; i++) {
        float4 t;
        t.x = o[4 * i + 0] * inv; t.y = o[4 * i + 1] * inv;
        t.z = o[4 * i + 2] * inv; t.w = o[4 * i + 3] * inv;
        *(float4*)(op + 4 * i) = t;
    }
}

// ---------------------------------------------------------------------------
// Fused residual add + LayerNorm (in place on x): x = LN(x + r) * g + be
// One block per row (768 cols), 256 threads, 3 cols/thread.
// ---------------------------------------------------------------------------
__global__ __launch_bounds__(256) void add_ln_kernel(
    float* __restrict__ x, const float* __restrict__ r,
    const float* __restrict__ g, const float* __restrict__ be)
{
    const int row = blockIdx.x;
    const int tid = threadIdx.x;
    float* xp = x + (size_t)row * D_;
    const float* rp = r + (size_t)row * D_;

    float v[3];
    float s1 = 0.f, s2 = 0.f;
#pragma unroll
    for (int i = 0; i < 3; i++) {
        const int c = tid + 256 * i;
        v[i] = xp[c] + rp[c];
        s1 += v[i];
        s2 += v[i] * v[i];
    }
#pragma unroll
    for (int off = 16; off; off >>= 1) {
        s1 += __shfl_xor_sync(0xffffffffu, s1, off);
        s2 += __shfl_xor_sync(0xffffffffu, s2, off);
    }
    __shared__ float r1[8], r2[8];
    if ((tid & 31) == 0) { r1[tid >> 5] = s1; r2[tid >> 5] = s2; }
    __syncthreads();
    s1 = 0.f; s2 = 0.f;
#pragma unroll
    for (int i = 0; i < 8; i++) { s1 += r1[i]; s2 += r2[i]; }

    const float mean = s1 * (1.f / 768.f);
    const float var  = s2 * (1.f / 768.f) - mean * mean;
    const float rstd = rsqrtf(var + 1e-5f);
#pragma unroll
    for (int i = 0; i < 3; i++) {
        const int c = tid + 256 * i;
        xp[c] = (v[i] - mean) * rstd * g[c] + be[c];
    }
}

// ---------------------------------------------------------------------------
// Host orchestration
// ---------------------------------------------------------------------------
static void run_gemm(const float* A, const float* W, const float* bias,
                     float* C, int M, int N, int K, int relu)
{
    dim3 grid(N / 128, M / 128);
    if (relu)
        sgemm_kernel<1><<<grid, 256>>>(A, W, bias, C, M, N, K);
    else
        sgemm_kernel<0><<<grid, 256>>>(A, W, bias, C, M, N, K);
}

extern "C" void kernel_launch(void* const* d_in, const int* in_sizes, int n_in,
                              void* d_out, int out_size)
{
    const float* src = (const float*)d_in[0];
    const float* qw  = (const float*)d_in[1];
    const float* qb  = (const float*)d_in[2];
    const float* kw  = (const float*)d_in[3];
    const float* kb  = (const float*)d_in[4];
    const float* vw  = (const float*)d_in[5];
    const float* vb  = (const float*)d_in[6];
    const float* ow  = (const float*)d_in[7];
    const float* ob  = (const float*)d_in[8];
    const float* w1  = (const float*)d_in[9];
    const float* b1  = (const float*)d_in[10];
    const float* w2  = (const float*)d_in[11];
    const float* b2  = (const float*)d_in[12];
    const float* g1  = (const float*)d_in[13];
    const float* be1 = (const float*)d_in[14];
    const float* g2  = (const float*)d_in[15];
    const float* be2 = (const float*)d_in[16];

    float *x, *q, *k, *v, *att, *tmp, *ff;
    cudaGetSymbolAddress((void**)&x,   g_x);
    cudaGetSymbolAddress((void**)&q,   g_q);
    cudaGetSymbolAddress((void**)&k,   g_k);
    cudaGetSymbolAddress((void**)&v,   g_v);
    cudaGetSymbolAddress((void**)&att, g_att);
    cudaGetSymbolAddress((void**)&tmp, g_tmp);
    cudaGetSymbolAddress((void**)&ff,  g_ff);

    const size_t xbytes = (size_t)MROWS * D_ * sizeof(float);
    cudaMemcpyAsync(x, src, xbytes, cudaMemcpyDeviceToDevice, 0);

    for (int l = 0; l < L_; l++) {
        const float* qwl = qw + (size_t)l * D_ * D_;
        const float* kwl = kw + (size_t)l * D_ * D_;
        const float* vwl = vw + (size_t)l * D_ * D_;
        const float* owl = ow + (size_t)l * D_ * D_;
        const float* w1l = w1 + (size_t)l * DFF_ * D_;
        const float* w2l = w2 + (size_t)l * D_ * DFF_;

        // projections
        run_gemm(x, qwl, qb + l * D_, q, MROWS, D_, D_, 0);
        run_gemm(x, kwl, kb + l * D_, k, MROWS, D_, D_, 0);
        run_gemm(x, vwl, vb + l * D_, v, MROWS, D_, D_, 0);

        // banded attention
        {
            dim3 grid(S_ / 128, H_, B_);
            attn_kernel<<<grid, 128>>>(q, k, v, att);
        }

        // output projection + residual LN
        run_gemm(att, owl, ob + l * D_, tmp, MROWS, D_, D_, 0);
        add_ln_kernel<<<MROWS, 256>>>(x, tmp, g1 + l * D_, be1 + l * D_);

        // FFN
        run_gemm(x, w1l, b1 + l * DFF_, ff, MROWS, DFF_, D_, 1);
        run_gemm(ff, w2l, b2 + l * D_, tmp, MROWS, D_, DFF_, 0);
        add_ln_kernel<<<MROWS, 256>>>(x, tmp, g2 + l * D_, be2 + l * D_);
    }

    cudaMemcpyAsync(d_out, x, xbytes, cudaMemcpyDeviceToDevice, 0);
}

// round 3
// speedup vs baseline: 1.8444x; 1.8444x over previous
#include <cuda_runtime.h>
#include <cuda_bf16.h>
#include <cstdint>

// Problem constants
#define B_ 2
#define S_ 2048
#define D_ 768
#define H_ 12
#define DH_ 64
#define L_ 2
#define DFF_ 3072
#define MROWS (B_ * S_)   // 4096

// ---------------------------------------------------------------------------
// Scratch (static device globals — no allocation allowed)
// ---------------------------------------------------------------------------
__device__ float g_x  [MROWS * D_];
__device__ float g_q  [MROWS * D_];
__device__ float g_k  [MROWS * D_];
__device__ float g_v  [MROWS * D_];
__device__ float g_att[MROWS * D_];
__device__ float g_tmp[MROWS * D_];
__device__ float g_ff [MROWS * DFF_];
// bf16 split buffers
__device__ __nv_bfloat16 g_ah[MROWS * DFF_];
__device__ __nv_bfloat16 g_al[MROWS * DFF_];
__device__ __nv_bfloat16 g_wh[DFF_ * D_];
__device__ __nv_bfloat16 g_wl[DFF_ * D_];

// ---------------------------------------------------------------------------
// Baseline-PTX tensor-core helpers (all valid on plain sm_103 target)
// ---------------------------------------------------------------------------
__device__ __forceinline__ uint32_t smem_u32(const void* p) {
    uint32_t a;
    asm("{ .reg .u64 t; cvta.to.shared.u64 t, %1; cvt.u32.u64 %0, t; }"
        : "=r"(a) : "l"(p));
    return a;
}

__device__ __forceinline__ void ldsm_x4(uint32_t& r0, uint32_t& r1,
                                        uint32_t& r2, uint32_t& r3, uint32_t a) {
    asm volatile("ldmatrix.sync.aligned.m8n8.x4.shared.b16 {%0,%1,%2,%3}, [%4];"
                 : "=r"(r0), "=r"(r1), "=r"(r2), "=r"(r3) : "r"(a));
}
__device__ __forceinline__ void ldsm_x2(uint32_t& r0, uint32_t& r1, uint32_t a) {
    asm volatile("ldmatrix.sync.aligned.m8n8.x2.shared.b16 {%0,%1}, [%2];"
                 : "=r"(r0), "=r"(r1) : "r"(a));
}
__device__ __forceinline__ void mma_bf16(float* d, const uint32_t* a, const uint32_t* b) {
    asm volatile(
        "mma.sync.aligned.m16n8k16.row.col.f32.bf16.bf16.f32 "
        "{%0,%1,%2,%3}, {%4,%5,%6,%7}, {%8,%9}, {%0,%1,%2,%3};"
        : "+f"(d[0]), "+f"(d[1]), "+f"(d[2]), "+f"(d[3])
        : "r"(a[0]), "r"(a[1]), "r"(a[2]), "r"(a[3]), "r"(b[0]), "r"(b[1]));
}
#define CP16(dst, src) \
    asm volatile("cp.async.cg.shared.global [%0], [%1], 16;" :: "r"(dst), "l"(src))
#define CP_COMMIT() asm volatile("cp.async.commit_group;" ::: "memory")
#define CP_WAIT1()  asm volatile("cp.async.wait_group 1;" ::: "memory")
#define CP_WAIT0()  asm volatile("cp.async.wait_group 0;" ::: "memory")

// ---------------------------------------------------------------------------
// Split fp32 -> bf16 hi + bf16 lo
// ---------------------------------------------------------------------------
__global__ __launch_bounds__(256) void split_kernel(
    const float* __restrict__ in, __nv_bfloat16* __restrict__ hi,
    __nv_bfloat16* __restrict__ lo, int n4)
{
    int i = blockIdx.x * blockDim.x + threadIdx.x;
    if (i >= n4) return;
    float4 x = ((const float4*)in)[i];
    __nv_bfloat16 h0 = __float2bfloat16(x.x), h1 = __float2bfloat16(x.y);
    __nv_bfloat16 h2 = __float2bfloat16(x.z), h3 = __float2bfloat16(x.w);
    __nv_bfloat16 l0 = __float2bfloat16(x.x - __bfloat162float(h0));
    __nv_bfloat16 l1 = __float2bfloat16(x.y - __bfloat162float(h1));
    __nv_bfloat16 l2 = __float2bfloat16(x.z - __bfloat162float(h2));
    __nv_bfloat16 l3 = __float2bfloat16(x.w - __bfloat162float(h3));
    __nv_bfloat162* hp = (__nv_bfloat162*)hi;
    __nv_bfloat162* lp = (__nv_bfloat162*)lo;
    hp[2 * i + 0] = __nv_bfloat162(h0, h1);
    hp[2 * i + 1] = __nv_bfloat162(h2, h3);
    lp[2 * i + 0] = __nv_bfloat162(l0, l1);
    lp[2 * i + 1] = __nv_bfloat162(l2, l3);
}

// ---------------------------------------------------------------------------
// mma.sync split-bf16 GEMM: C[M,N] = A[M,K] @ W[N,K]^T + bias (optional relu)
// 128x128 CTA tile, BK=32, 8 warps (2x4), warp tile 64x32.
// Smem rows padded to 40 elems (80B) -> conflict-free ldmatrix.
// cp.async double-buffered K pipeline.
// ---------------------------------------------------------------------------
#define RS_E 40              // smem row stride in bf16 elems
#define RS_B 80              // in bytes
#define TILE_B (128 * RS_B)  // 10240 bytes per tile
#define STAGE_B (4 * TILE_B) // Ah, Al, Bh, Bl
#define GEMM_SMEM (2 * STAGE_B)  // 81920

template <int EPI>
__global__ __launch_bounds__(256) void gemm_mma_kernel(
    const __nv_bfloat16* __restrict__ Ah, const __nv_bfloat16* __restrict__ Al,
    const __nv_bfloat16* __restrict__ Wh, const __nv_bfloat16* __restrict__ Wl,
    const float* __restrict__ bias, float* __restrict__ C,
    int M, int N, int K)
{
    extern __shared__ char smem[];
    const uint32_t sb = smem_u32(smem);

    const int tid = threadIdx.x;
    const int wid = tid >> 5;
    const int lane = tid & 31;
    const int warp_m = wid >> 2;   // 0..1
    const int warp_n = wid & 3;    // 0..3
    const int bm = blockIdx.y * 128;
    const int bn = blockIdx.x * 128;

    float acc[4][4][4];
#pragma unroll
    for (int mi = 0; mi < 4; mi++)
#pragma unroll
        for (int ni = 0; ni < 4; ni++)
#pragma unroll
            for (int r = 0; r < 4; r++) acc[mi][ni][r] = 0.f;

    // loader indices: 2 x 16B per tile per thread
    const int i0 = tid, i1 = tid + 256;
    const int lr0 = i0 >> 2, ls0 = i0 & 3;
    const int lr1 = i1 >> 2, ls1 = i1 & 3;

    auto load_chunk = [&](int kc, int stage) {
        const uint32_t base = sb + stage * STAGE_B;
        const size_t a0 = (size_t)(bm + lr0) * K + kc + ls0 * 8;
        const size_t a1 = (size_t)(bm + lr1) * K + kc + ls1 * 8;
        const size_t b0 = (size_t)(bn + lr0) * K + kc + ls0 * 8;
        const size_t b1 = (size_t)(bn + lr1) * K + kc + ls1 * 8;
        const uint32_t d0 = lr0 * RS_B + ls0 * 16;
        const uint32_t d1 = lr1 * RS_B + ls1 * 16;
        CP16(base + d0,              Ah + a0);
        CP16(base + d1,              Ah + a1);
        CP16(base + TILE_B + d0,     Al + a0);
        CP16(base + TILE_B + d1,     Al + a1);
        CP16(base + 2 * TILE_B + d0, Wh + b0);
        CP16(base + 2 * TILE_B + d1, Wh + b1);
        CP16(base + 3 * TILE_B + d0, Wl + b0);
        CP16(base + 3 * TILE_B + d1, Wl + b1);
    };

    // ldmatrix lane addressing
    const int arow = warp_m * 64 + (lane & 15);
    const int akb  = (lane >> 4) * 8;            // k offset 0/8
    const int brow = warp_n * 32 + (lane & 7);
    const int bkb  = ((lane >> 3) & 1) * 8;

    auto compute = [&](int stage) {
        const uint32_t base = sb + stage * STAGE_B;
        const uint32_t pAh = base;
        const uint32_t pAl = base + TILE_B;
        const uint32_t pBh = base + 2 * TILE_B;
        const uint32_t pBl = base + 3 * TILE_B;
#pragma unroll
        for (int ks = 0; ks < 2; ks++) {
            const int k0 = ks * 16;
            uint32_t ah[4][4], al[4][4], bh[4][2], bl[4][2];
#pragma unroll
            for (int mi = 0; mi < 4; mi++) {
                const uint32_t ro = (uint32_t)(arow + mi * 16) * RS_B + (k0 + akb) * 2;
                ldsm_x4(ah[mi][0], ah[mi][1], ah[mi][2], ah[mi][3], pAh + ro);
                ldsm_x4(al[mi][0], al[mi][1], al[mi][2], al[mi][3], pAl + ro);
            }
#pragma unroll
            for (int ni = 0; ni < 4; ni++) {
                const uint32_t ro = (uint32_t)(brow + ni * 8) * RS_B + (k0 + bkb) * 2;
                ldsm_x2(bh[ni][0], bh[ni][1], pBh + ro);
                ldsm_x2(bl[ni][0], bl[ni][1], pBl + ro);
            }
#pragma unroll
            for (int mi = 0; mi < 4; mi++)
#pragma unroll
                for (int ni = 0; ni < 4; ni++) {
                    mma_bf16(acc[mi][ni], ah[mi], bh[ni]);
                    mma_bf16(acc[mi][ni], ah[mi], bl[ni]);
                    mma_bf16(acc[mi][ni], al[mi], bh[ni]);
                }
        }
    };

    const int nchunks = K >> 5;
    load_chunk(0, 0);
    CP_COMMIT();
    for (int c = 0; c < nchunks; c++) {
        if (c + 1 < nchunks) {
            load_chunk((c + 1) << 5, (c + 1) & 1);
            CP_COMMIT();
            CP_WAIT1();
        } else {
            CP_WAIT0();
        }
        __syncthreads();
        compute(c & 1);
        __syncthreads();
    }

    // epilogue
#pragma unroll
    for (int mi = 0; mi < 4; mi++) {
        const int m0 = bm + warp_m * 64 + mi * 16 + (lane >> 2);
#pragma unroll
        for (int ni = 0; ni < 4; ni++) {
            const int n0 = bn + warp_n * 32 + ni * 8 + (lane & 3) * 2;
            const float bx = bias[n0], by = bias[n0 + 1];
            float2 v0, v1;
            v0.x = acc[mi][ni][0] + bx; v0.y = acc[mi][ni][1] + by;
            v1.x = acc[mi][ni][2] + bx; v1.y = acc[mi][ni][3] + by;
            if (EPI == 1) {
                v0.x = fmaxf(v0.x, 0.f); v0.y = fmaxf(v0.y, 0.f);
                v1.x = fmaxf(v1.x, 0.f); v1.y = fmaxf(v1.y, 0.f);
            }
            *(float2*)(C + (size_t)m0 * N + n0) = v0;
            *(float2*)(C + (size_t)(m0 + 8) * N + n0) = v1;
        }
    }
}

// ---------------------------------------------------------------------------
// Banded flash attention (unchanged from R1)
// ---------------------------------------------------------------------------
__global__ __launch_bounds__(128) void attn_kernel(
    const float* __restrict__ Q, const float* __restrict__ Kx,
    const float* __restrict__ Vx, float* __restrict__ O)
{
    __shared__ float Ks[64][64];
    __shared__ float Vs[64][64];

    const int b = blockIdx.z;
    const int h = blockIdx.y;
    const int q0 = blockIdx.x * 128;
    const int tid = threadIdx.x;
    const int qi = q0 + tid;

    const float scale = 0.125f;
    float q[64];
    {
        const float* qp = Q + (size_t)(b * S_ + qi) * D_ + h * DH_;
#pragma unroll
        for (int i = 0; i < 16; i++) {
            float4 t = *(const float4*)(qp + 4 * i);
            q[4 * i + 0] = t.x * scale; q[4 * i + 1] = t.y * scale;
            q[4 * i + 2] = t.z * scale; q[4 * i + 3] = t.w * scale;
        }
    }
    float o[64];
#pragma unroll
    for (int i = 0; i < 64; i++) o[i] = 0.f;
    float mmax = -1e30f, lsum = 0.f;

    int ks0 = q0 - 256; if (ks0 < 0) ks0 = 0;
    int ke  = q0 + 128 + 256; if (ke > S_) ke = S_;

    for (int ks = ks0; ks < ke; ks += 64) {
        const int row = tid >> 1;
        const int c0  = (tid & 1) * 32;
        const float* kp = Kx + (size_t)(b * S_ + ks + row) * D_ + h * DH_ + c0;
        const float* vp = Vx + (size_t)(b * S_ + ks + row) * D_ + h * DH_ + c0;
#pragma unroll
        for (int i = 0; i < 8; i++) {
            *(float4*)&Ks[row][c0 + 4 * i] = *(const float4*)(kp + 4 * i);
            *(float4*)&Vs[row][c0 + 4 * i] = *(const float4*)(vp + 4 * i);
        }
        __syncthreads();

        int jlo = qi - 256 - ks; if (jlo < 0) jlo = 0;
        int jhi = qi + 256 - ks; if (jhi > 63) jhi = 63;
        for (int j = jlo; j <= jhi; j++) {
            float s = 0.f;
#pragma unroll
            for (int i2 = 0; i2 < 16; i2++) {
                float4 kv = *(const float4*)&Ks[j][4 * i2];
                s += q[4 * i2 + 0] * kv.x + q[4 * i2 + 1] * kv.y
                   + q[4 * i2 + 2] * kv.z + q[4 * i2 + 3] * kv.w;
            }
            float mn = fmaxf(mmax, s);
            float p = __expf(s - mn);
            if (mn > mmax) {
                float corr = __expf(mmax - mn);
                lsum *= corr;
#pragma unroll
                for (int i2 = 0; i2 < 64; i2++) o[i2] *= corr;
                mmax = mn;
            }
            lsum += p;
#pragma unroll
            for (int i2 = 0; i2 < 16; i2++) {
                float4 vv = *(const float4*)&Vs[j][4 * i2];
                o[4 * i2 + 0] += p * vv.x; o[4 * i2 + 1] += p * vv.y;
                o[4 * i2 + 2] += p * vv.z; o[4 * i2 + 3] += p * vv.w;
            }
        }
        __syncthreads();
    }

    const float inv = 1.f / lsum;
    float* op = O + (size_t)(b * S_ + qi) * D_ + h * DH_;
#pragma unroll
    for (int i = 0; i < 16; i++) {
        float4 t;
        t.x = o[4 * i + 0] * inv; t.y = o[4 * i + 1] * inv;
        t.z = o[4 * i + 2] * inv; t.w = o[4 * i + 3] * inv;
        *(float4*)(op + 4 * i) = t;
    }
}

// ---------------------------------------------------------------------------
// Fused residual add + LayerNorm (in place on x)
// ---------------------------------------------------------------------------
__global__ __launch_bounds__(256) void add_ln_kernel(
    float* __restrict__ x, const float* __restrict__ r,
    const float* __restrict__ g, const float* __restrict__ be)
{
    const int row = blockIdx.x;
    const int tid = threadIdx.x;
    float* xp = x + (size_t)row * D_;
    const float* rp = r + (size_t)row * D_;

    float v[3];
    float s1 = 0.f, s2 = 0.f;
#pragma unroll
    for (int i = 0; i < 3; i++) {
        const int c = tid + 256 * i;
        v[i] = xp[c] + rp[c];
        s1 += v[i];
        s2 += v[i] * v[i];
    }
#pragma unroll
    for (int off = 16; off; off >>= 1) {
        s1 += __shfl_xor_sync(0xffffffffu, s1, off);
        s2 += __shfl_xor_sync(0xffffffffu, s2, off);
    }
    __shared__ float r1[8], r2[8];
    if ((tid & 31) == 0) { r1[tid >> 5] = s1; r2[tid >> 5] = s2; }
    __syncthreads();
    s1 = 0.f; s2 = 0.f;
#pragma unroll
    for (int i = 0; i < 8; i++) { s1 += r1[i]; s2 += r2[i]; }

    const float mean = s1 * (1.f / 768.f);
    const float var  = s2 * (1.f / 768.f) - mean * mean;
    const float rstd = rsqrtf(var + 1e-5f);
#pragma unroll
    for (int i = 0; i < 3; i++) {
        const int c = tid + 256 * i;
        xp[c] = (v[i] - mean) * rstd * g[c] + be[c];
    }
}

// ---------------------------------------------------------------------------
// Host orchestration
// ---------------------------------------------------------------------------
static void run_split(const float* in, __nv_bfloat16* hi, __nv_bfloat16* lo, int n)
{
    int n4 = n >> 2;
    split_kernel<<<(n4 + 255) / 256, 256>>>(in, hi, lo, n4);
}

static void run_gemm_tc(const __nv_bfloat16* Ah, const __nv_bfloat16* Al,
                        const __nv_bfloat16* Wh, const __nv_bfloat16* Wl,
                        const float* bias, float* C, int M, int N, int K, int relu)
{
    dim3 grid(N / 128, M / 128);
    if (relu)
        gemm_mma_kernel<1><<<grid, 256, GEMM_SMEM>>>(Ah, Al, Wh, Wl, bias, C, M, N, K);
    else
        gemm_mma_kernel<0><<<grid, 256, GEMM_SMEM>>>(Ah, Al, Wh, Wl, bias, C, M, N, K);
}

extern "C" void kernel_launch(void* const* d_in, const int* in_sizes, int n_in,
                              void* d_out, int out_size)
{
    const float* src = (const float*)d_in[0];
    const float* qw  = (const float*)d_in[1];
    const float* qb  = (const float*)d_in[2];
    const float* kw  = (const float*)d_in[3];
    const float* kb  = (const float*)d_in[4];
    const float* vw  = (const float*)d_in[5];
    const float* vb  = (const float*)d_in[6];
    const float* ow  = (const float*)d_in[7];
    const float* ob  = (const float*)d_in[8];
    const float* w1  = (const float*)d_in[9];
    const float* b1  = (const float*)d_in[10];
    const float* w2  = (const float*)d_in[11];
    const float* b2  = (const float*)d_in[12];
    const float* g1  = (const float*)d_in[13];
    const float* be1 = (const float*)d_in[14];
    const float* g2  = (const float*)d_in[15];
    const float* be2 = (const float*)d_in[16];

    cudaFuncSetAttribute(gemm_mma_kernel<0>,
                         cudaFuncAttributeMaxDynamicSharedMemorySize, GEMM_SMEM);
    cudaFuncSetAttribute(gemm_mma_kernel<1>,
                         cudaFuncAttributeMaxDynamicSharedMemorySize, GEMM_SMEM);

    float *x, *q, *k, *v, *att, *tmp, *ff;
    __nv_bfloat16 *ah, *al, *wh, *wl;
    cudaGetSymbolAddress((void**)&x,   g_x);
    cudaGetSymbolAddress((void**)&q,   g_q);
    cudaGetSymbolAddress((void**)&k,   g_k);
    cudaGetSymbolAddress((void**)&v,   g_v);
    cudaGetSymbolAddress((void**)&att, g_att);
    cudaGetSymbolAddress((void**)&tmp, g_tmp);
    cudaGetSymbolAddress((void**)&ff,  g_ff);
    cudaGetSymbolAddress((void**)&ah,  g_ah);
    cudaGetSymbolAddress((void**)&al,  g_al);
    cudaGetSymbolAddress((void**)&wh,  g_wh);
    cudaGetSymbolAddress((void**)&wl,  g_wl);

    const size_t xbytes = (size_t)MROWS * D_ * sizeof(float);
    cudaMemcpyAsync(x, src, xbytes, cudaMemcpyDeviceToDevice, 0);

    for (int l = 0; l < L_; l++) {
        const float* qwl = qw + (size_t)l * D_ * D_;
        const float* kwl = kw + (size_t)l * D_ * D_;
        const float* vwl = vw + (size_t)l * D_ * D_;
        const float* owl = ow + (size_t)l * D_ * D_;
        const float* w1l = w1 + (size_t)l * DFF_ * D_;
        const float* w2l = w2 + (size_t)l * D_ * DFF_;

        // projections (split x once, reuse for q/k/v)
        run_split(x, ah, al, MROWS * D_);
        run_split(qwl, wh, wl, D_ * D_);
        run_gemm_tc(ah, al, wh, wl, qb + l * D_, q, MROWS, D_, D_, 0);
        run_split(kwl, wh, wl, D_ * D_);
        run_gemm_tc(ah, al, wh, wl, kb + l * D_, k, MROWS, D_, D_, 0);
        run_split(vwl, wh, wl, D_ * D_);
        run_gemm_tc(ah, al, wh, wl, vb + l * D_, v, MROWS, D_, D_, 0);

        // banded attention
        {
            dim3 grid(S_ / 128, H_, B_);
            attn_kernel<<<grid, 128>>>(q, k, v, att);
        }

        // output projection + residual LN
        run_split(att, ah, al, MROWS * D_);
        run_split(owl, wh, wl, D_ * D_);
        run_gemm_tc(ah, al, wh, wl, ob + l * D_, tmp, MROWS, D_, D_, 0);
        add_ln_kernel<<<MROWS, 256>>>(x, tmp, g1 + l * D_, be1 + l * D_);

        // FFN
        run_split(x, ah, al, MROWS * D_);
        run_split(w1l, wh, wl, DFF_ * D_);
        run_gemm_tc(ah, al, wh, wl, b1 + l * DFF_, ff, MROWS, DFF_, D_, 1);
        run_split(ff, ah, al, MROWS * DFF_);
        run_split(w2l, wh, wl, D_ * DFF_);
        run_gemm_tc(ah, al, wh, wl, b2 + l * D_, tmp, MROWS, D_, DFF_, 0);
        add_ln_kernel<<<MROWS, 256>>>(x, tmp, g2 + l * D_, be2 + l * D_);
    }

    cudaMemcpyAsync(d_out, x, xbytes, cudaMemcpyDeviceToDevice, 0);
}

// round 4
// speedup vs baseline: 2.7234x; 1.4766x over previous
#include <cuda_runtime.h>
#include <cuda_bf16.h>
#include <cstdint>

// Problem constants
#define B_ 2
#define S_ 2048
#define D_ 768
#define H_ 12
#define DH_ 64
#define L_ 2
#define DFF_ 3072
#define MROWS (B_ * S_)   // 4096

// ---------------------------------------------------------------------------
// Scratch (static device globals — no allocation allowed)
// ---------------------------------------------------------------------------
__device__ float g_x  [MROWS * D_];
__device__ float g_tmp[MROWS * D_];
__device__ __nv_bfloat16 g_xh[MROWS * D_];
__device__ __nv_bfloat16 g_xl[MROWS * D_];
__device__ __nv_bfloat16 g_qh[MROWS * D_];
__device__ __nv_bfloat16 g_ql[MROWS * D_];
__device__ __nv_bfloat16 g_kh[MROWS * D_];
__device__ __nv_bfloat16 g_kl[MROWS * D_];
__device__ __nv_bfloat16 g_vh[MROWS * D_];
__device__ __nv_bfloat16 g_oh[MROWS * D_];
__device__ __nv_bfloat16 g_ol[MROWS * D_];
__device__ __nv_bfloat16 g_ffh[MROWS * DFF_];
__device__ __nv_bfloat16 g_ffl[MROWS * DFF_];
__device__ __nv_bfloat16 g_wh[DFF_ * D_];
__device__ __nv_bfloat16 g_wl[DFF_ * D_];

// ---------------------------------------------------------------------------
// Baseline-PTX tensor-core helpers
// ---------------------------------------------------------------------------
__device__ __forceinline__ uint32_t smem_u32(const void* p) {
    uint32_t a;
    asm("{ .reg .u64 t; cvta.to.shared.u64 t, %1; cvt.u32.u64 %0, t; }"
        : "=r"(a) : "l"(p));
    return a;
}
__device__ __forceinline__ void ldsm_x4(uint32_t& r0, uint32_t& r1,
                                        uint32_t& r2, uint32_t& r3, uint32_t a) {
    asm volatile("ldmatrix.sync.aligned.m8n8.x4.shared.b16 {%0,%1,%2,%3}, [%4];"
                 : "=r"(r0), "=r"(r1), "=r"(r2), "=r"(r3) : "r"(a));
}
__device__ __forceinline__ void ldsm_x2(uint32_t& r0, uint32_t& r1, uint32_t a) {
    asm volatile("ldmatrix.sync.aligned.m8n8.x2.shared.b16 {%0,%1}, [%2];"
                 : "=r"(r0), "=r"(r1) : "r"(a));
}
__device__ __forceinline__ void ldsm_x2t(uint32_t& r0, uint32_t& r1, uint32_t a) {
    asm volatile("ldmatrix.sync.aligned.m8n8.x2.trans.shared.b16 {%0,%1}, [%2];"
                 : "=r"(r0), "=r"(r1) : "r"(a));
}
__device__ __forceinline__ void mma_bf16(float* d, const uint32_t* a, const uint32_t* b) {
    asm volatile(
        "mma.sync.aligned.m16n8k16.row.col.f32.bf16.bf16.f32 "
        "{%0,%1,%2,%3}, {%4,%5,%6,%7}, {%8,%9}, {%0,%1,%2,%3};"
        : "+f"(d[0]), "+f"(d[1]), "+f"(d[2]), "+f"(d[3])
        : "r"(a[0]), "r"(a[1]), "r"(a[2]), "r"(a[3]), "r"(b[0]), "r"(b[1]));
}
#define CP16(dst, src) \
    asm volatile("cp.async.cg.shared.global [%0], [%1], 16;" :: "r"(dst), "l"(src))
#define CP_COMMIT() asm volatile("cp.async.commit_group;" ::: "memory")
#define CP_WAIT1()  asm volatile("cp.async.wait_group 1;" ::: "memory")
#define CP_WAIT0()  asm volatile("cp.async.wait_group 0;" ::: "memory")

__device__ __forceinline__ uint32_t packbf(float a, float b) {
    __nv_bfloat162 t = __floats2bfloat162_rn(a, b);
    return *(uint32_t*)&t;
}

// ---------------------------------------------------------------------------
// Split fp32 -> bf16 hi + bf16 lo (weights + initial src only)
// ---------------------------------------------------------------------------
__global__ __launch_bounds__(256) void split_kernel(
    const float* __restrict__ in, __nv_bfloat16* __restrict__ hi,
    __nv_bfloat16* __restrict__ lo, int n4)
{
    int i = blockIdx.x * blockDim.x + threadIdx.x;
    if (i >= n4) return;
    float4 x = ((const float4*)in)[i];
    __nv_bfloat16 h0 = __float2bfloat16(x.x), h1 = __float2bfloat16(x.y);
    __nv_bfloat16 h2 = __float2bfloat16(x.z), h3 = __float2bfloat16(x.w);
    __nv_bfloat16 l0 = __float2bfloat16(x.x - __bfloat162float(h0));
    __nv_bfloat16 l1 = __float2bfloat16(x.y - __bfloat162float(h1));
    __nv_bfloat16 l2 = __float2bfloat16(x.z - __bfloat162float(h2));
    __nv_bfloat16 l3 = __float2bfloat16(x.w - __bfloat162float(h3));
    __nv_bfloat162* hp = (__nv_bfloat162*)hi;
    __nv_bfloat162* lp = (__nv_bfloat162*)lo;
    hp[2 * i + 0] = __nv_bfloat162(h0, h1);
    hp[2 * i + 1] = __nv_bfloat162(h2, h3);
    lp[2 * i + 0] = __nv_bfloat162(l0, l1);
    lp[2 * i + 1] = __nv_bfloat162(l2, l3);
}

// ---------------------------------------------------------------------------
// mma.sync split-bf16 GEMM: 128x128 CTA tile, BK=32, 8 warps, warp 64x32.
// EPI: 0 = fp32 C (+bias); 1 = split hi/lo (+bias); 2 = relu + split hi/lo;
//      3 = bf16 hi only (+bias)
// ---------------------------------------------------------------------------
#define RS_B 80              // smem row stride bytes (40 bf16)
#define TILE_B (128 * RS_B)
#define STAGE_B (4 * TILE_B)
#define GEMM_SMEM (2 * STAGE_B)  // 81920

template <int EPI>
__global__ __launch_bounds__(256) void gemm_mma_kernel(
    const __nv_bfloat16* __restrict__ Ah, const __nv_bfloat16* __restrict__ Al,
    const __nv_bfloat16* __restrict__ Wh, const __nv_bfloat16* __restrict__ Wl,
    const float* __restrict__ bias, float* __restrict__ C,
    __nv_bfloat16* __restrict__ Hi, __nv_bfloat16* __restrict__ Lo,
    int M, int N, int K)
{
    extern __shared__ char smem[];
    const uint32_t sb = smem_u32(smem);

    const int tid = threadIdx.x;
    const int wid = tid >> 5;
    const int lane = tid & 31;
    const int warp_m = wid >> 2;
    const int warp_n = wid & 3;
    const int bm = blockIdx.y * 128;
    const int bn = blockIdx.x * 128;

    float acc[4][4][4];
#pragma unroll
    for (int mi = 0; mi < 4; mi++)
#pragma unroll
        for (int ni = 0; ni < 4; ni++)
#pragma unroll
            for (int r = 0; r < 4; r++) acc[mi][ni][r] = 0.f;

    const int i0 = tid, i1 = tid + 256;
    const int lr0 = i0 >> 2, ls0 = i0 & 3;
    const int lr1 = i1 >> 2, ls1 = i1 & 3;

    auto load_chunk = [&](int kc, int stage) {
        const uint32_t base = sb + stage * STAGE_B;
        const size_t a0 = (size_t)(bm + lr0) * K + kc + ls0 * 8;
        const size_t a1 = (size_t)(bm + lr1) * K + kc + ls1 * 8;
        const size_t b0 = (size_t)(bn + lr0) * K + kc + ls0 * 8;
        const size_t b1 = (size_t)(bn + lr1) * K + kc + ls1 * 8;
        const uint32_t d0 = lr0 * RS_B + ls0 * 16;
        const uint32_t d1 = lr1 * RS_B + ls1 * 16;
        CP16(base + d0,              Ah + a0);
        CP16(base + d1,              Ah + a1);
        CP16(base + TILE_B + d0,     Al + a0);
        CP16(base + TILE_B + d1,     Al + a1);
        CP16(base + 2 * TILE_B + d0, Wh + b0);
        CP16(base + 2 * TILE_B + d1, Wh + b1);
        CP16(base + 3 * TILE_B + d0, Wl + b0);
        CP16(base + 3 * TILE_B + d1, Wl + b1);
    };

    const int arow = warp_m * 64 + (lane & 15);
    const int akb  = (lane >> 4) * 8;
    const int brow = warp_n * 32 + (lane & 7);
    const int bkb  = ((lane >> 3) & 1) * 8;

    auto compute = [&](int stage) {
        const uint32_t base = sb + stage * STAGE_B;
        const uint32_t pAh = base;
        const uint32_t pAl = base + TILE_B;
        const uint32_t pBh = base + 2 * TILE_B;
        const uint32_t pBl = base + 3 * TILE_B;
#pragma unroll
        for (int ks = 0; ks < 2; ks++) {
            const int k0 = ks * 16;
            uint32_t ah[4][4], al[4][4], bh[4][2], bl[4][2];
#pragma unroll
            for (int mi = 0; mi < 4; mi++) {
                const uint32_t ro = (uint32_t)(arow + mi * 16) * RS_B + (k0 + akb) * 2;
                ldsm_x4(ah[mi][0], ah[mi][1], ah[mi][2], ah[mi][3], pAh + ro);
                ldsm_x4(al[mi][0], al[mi][1], al[mi][2], al[mi][3], pAl + ro);
            }
#pragma unroll
            for (int ni = 0; ni < 4; ni++) {
                const uint32_t ro = (uint32_t)(brow + ni * 8) * RS_B + (k0 + bkb) * 2;
                ldsm_x2(bh[ni][0], bh[ni][1], pBh + ro);
                ldsm_x2(bl[ni][0], bl[ni][1], pBl + ro);
            }
#pragma unroll
            for (int mi = 0; mi < 4; mi++)
#pragma unroll
                for (int ni = 0; ni < 4; ni++) {
                    mma_bf16(acc[mi][ni], ah[mi], bh[ni]);
                    mma_bf16(acc[mi][ni], ah[mi], bl[ni]);
                    mma_bf16(acc[mi][ni], al[mi], bh[ni]);
                }
        }
    };

    const int nchunks = K >> 5;
    load_chunk(0, 0);
    CP_COMMIT();
    for (int c = 0; c < nchunks; c++) {
        if (c + 1 < nchunks) {
            load_chunk((c + 1) << 5, (c + 1) & 1);
            CP_COMMIT();
            CP_WAIT1();
        } else {
            CP_WAIT0();
        }
        __syncthreads();
        compute(c & 1);
        __syncthreads();
    }

    // epilogue
#pragma unroll
    for (int mi = 0; mi < 4; mi++) {
        const int m0 = bm + warp_m * 64 + mi * 16 + (lane >> 2);
#pragma unroll
        for (int ni = 0; ni < 4; ni++) {
            const int n0 = bn + warp_n * 32 + ni * 8 + (lane & 3) * 2;
            const float bx = bias[n0], by = bias[n0 + 1];
            float v00 = acc[mi][ni][0] + bx, v01 = acc[mi][ni][1] + by;
            float v10 = acc[mi][ni][2] + bx, v11 = acc[mi][ni][3] + by;
            if (EPI == 2) {
                v00 = fmaxf(v00, 0.f); v01 = fmaxf(v01, 0.f);
                v10 = fmaxf(v10, 0.f); v11 = fmaxf(v11, 0.f);
            }
            if (EPI == 0) {
                *(float2*)(C + (size_t)m0 * N + n0) = make_float2(v00, v01);
                *(float2*)(C + (size_t)(m0 + 8) * N + n0) = make_float2(v10, v11);
            } else if (EPI == 3) {
                *(uint32_t*)(Hi + (size_t)m0 * N + n0) = packbf(v00, v01);
                *(uint32_t*)(Hi + (size_t)(m0 + 8) * N + n0) = packbf(v10, v11);
            } else {
                uint32_t h0 = packbf(v00, v01);
                uint32_t h1 = packbf(v10, v11);
                __nv_bfloat162 hb0 = *(__nv_bfloat162*)&h0;
                __nv_bfloat162 hb1 = *(__nv_bfloat162*)&h1;
                uint32_t l0 = packbf(v00 - __bfloat162float(hb0.x),
                                     v01 - __bfloat162float(hb0.y));
                uint32_t l1 = packbf(v10 - __bfloat162float(hb1.x),
                                     v11 - __bfloat162float(hb1.y));
                *(uint32_t*)(Hi + (size_t)m0 * N + n0) = h0;
                *(uint32_t*)(Hi + (size_t)(m0 + 8) * N + n0) = h1;
                *(uint32_t*)(Lo + (size_t)m0 * N + n0) = l0;
                *(uint32_t*)(Lo + (size_t)(m0 + 8) * N + n0) = l1;
            }
        }
    }
}

// ---------------------------------------------------------------------------
// Tensor-core banded flash attention.
// CTA = (qtile of 128, head, batch); 8 warps x 16 q-rows.
// K-tiles of 128 keys, double-buffered cp.async. QK^T split-bf16 (3 mma),
// online softmax on fragments, P·V plain bf16 with ldmatrix.trans.
// Band: |i-j| <= 256. Emits O as bf16 hi/lo.
// ---------------------------------------------------------------------------
#define ATT_RSB 144                 // row stride bytes (72 bf16, 64 used)
#define ATT_TILE_B (128 * ATT_RSB)  // 18432
#define ATT_SMEM (8 * ATT_TILE_B)   // Qh,Ql + 2 stages x (Kh,Kl,V) = 147456

__global__ __launch_bounds__(256) void attn_mma_kernel(
    const __nv_bfloat16* __restrict__ Qh, const __nv_bfloat16* __restrict__ Ql,
    const __nv_bfloat16* __restrict__ Kh, const __nv_bfloat16* __restrict__ Kl,
    const __nv_bfloat16* __restrict__ Vh,
    __nv_bfloat16* __restrict__ Oh, __nv_bfloat16* __restrict__ Ol)
{
    extern __shared__ char smem[];
    const uint32_t sb = smem_u32(smem);
    const int b = blockIdx.z;
    const int h = blockIdx.y;
    const int qt = blockIdx.x;
    const int q0 = qt * 128;
    const int tid = threadIdx.x;
    const int wid = tid >> 5;
    const int lane = tid & 31;
    const int g = lane >> 2;
    const int tq = lane & 3;

    const uint32_t sQh = sb;
    const uint32_t sQl = sb + ATT_TILE_B;
    const uint32_t sKV0 = sb + 2 * ATT_TILE_B;  // stage s at sKV0 + s*3*ATT_TILE_B

    // stage Q (Qh, Ql): 2 tiles, 8 CP16 per thread
    {
        const int row = tid >> 3, seg = tid & 7;
#pragma unroll
        for (int t = 0; t < 4; t++) {
            const int r = row + t * 32;
            const size_t go = (size_t)(b * S_ + q0 + r) * D_ + h * 64 + seg * 8;
            const uint32_t so = (uint32_t)r * ATT_RSB + seg * 16;
            CP16(sQh + so, Qh + go);
            CP16(sQl + so, Ql + go);
        }
    }
    CP_COMMIT();

    const int kt_lo = (qt - 2 < 0) ? 0 : qt - 2;
    const int kt_hi = (qt + 2 > S_ / 128 - 1) ? S_ / 128 - 1 : qt + 2;

    auto load_kv = [&](int kt, int stg) {
        const uint32_t base = sKV0 + stg * 3 * ATT_TILE_B;
        const int row = tid >> 3, seg = tid & 7;
#pragma unroll
        for (int t = 0; t < 4; t++) {
            const int r = row + t * 32;
            const size_t go = (size_t)(b * S_ + kt * 128 + r) * D_ + h * 64 + seg * 8;
            const uint32_t so = (uint32_t)r * ATT_RSB + seg * 16;
            CP16(base + so,                  Kh + go);
            CP16(base + ATT_TILE_B + so,     Kl + go);
            CP16(base + 2 * ATT_TILE_B + so, Vh + go);
        }
    };
    load_kv(kt_lo, 0);
    CP_COMMIT();

    CP_WAIT1();      // Q ready (kv0 may be in flight)
    __syncthreads();

    // Q A-fragments (held in registers entire kernel)
    uint32_t qhf[4][4], qlf[4][4];
    {
        const int arow = wid * 16 + (lane & 15);
        const int akb = (lane >> 4) * 8;
#pragma unroll
        for (int ks = 0; ks < 4; ks++) {
            const uint32_t ro = (uint32_t)arow * ATT_RSB + (ks * 16 + akb) * 2;
            ldsm_x4(qhf[ks][0], qhf[ks][1], qhf[ks][2], qhf[ks][3], sQh + ro);
            ldsm_x4(qlf[ks][0], qlf[ks][1], qlf[ks][2], qlf[ks][3], sQl + ro);
        }
    }

    float m0 = -1e30f, m1 = -1e30f, l0 = 0.f, l1 = 0.f;
    float o[8][4];
#pragma unroll
    for (int nd = 0; nd < 8; nd++)
#pragma unroll
        for (int r = 0; r < 4; r++) o[nd][r] = 0.f;

    const int row0 = q0 + wid * 16 + g;   // row1 = row0 + 8
    const int brow0 = lane & 7;
    const int bkb = ((lane >> 3) & 1) * 8;
    const int vrow = lane & 15;

    for (int kt = kt_lo; kt <= kt_hi; kt++) {
        const int i = kt - kt_lo;
        const int stg = i & 1;
        if (kt < kt_hi) {
            load_kv(kt + 1, stg ^ 1);
            CP_COMMIT();
            CP_WAIT1();
        } else {
            CP_WAIT0();
        }
        __syncthreads();

        const uint32_t base = sKV0 + stg * 3 * ATT_TILE_B;
        const uint32_t pKh = base, pKl = base + ATT_TILE_B, pV = base + 2 * ATT_TILE_B;

        // S = QK^T (split: Qh*Kh + Qh*Kl + Ql*Kh), S[16 rows][128 keys]
        float s[16][4];
#pragma unroll
        for (int nt = 0; nt < 16; nt++)
#pragma unroll
            for (int r = 0; r < 4; r++) s[nt][r] = 0.f;
#pragma unroll
        for (int ks = 0; ks < 4; ks++) {
#pragma unroll
            for (int nt = 0; nt < 16; nt++) {
                uint32_t bh[2], bl[2];
                const uint32_t ro = (uint32_t)(nt * 8 + brow0) * ATT_RSB + (ks * 16 + bkb) * 2;
                ldsm_x2(bh[0], bh[1], pKh + ro);
                ldsm_x2(bl[0], bl[1], pKl + ro);
                mma_bf16(s[nt], qhf[ks], bh);
                mma_bf16(s[nt], qhf[ks], bl);
                mma_bf16(s[nt], qlf[ks], bh);
            }
        }

        // scale + band mask + row max
        float rmax0 = -1e30f, rmax1 = -1e30f;
#pragma unroll
        for (int nt = 0; nt < 16; nt++) {
            const int col = kt * 128 + nt * 8 + tq * 2;
            const bool i00 = (unsigned)(row0 - col + 256) <= 512u;
            const bool i01 = (unsigned)(row0 - col - 1 + 256) <= 512u;
            const bool i10 = (unsigned)(row0 + 8 - col + 256) <= 512u;
            const bool i11 = (unsigned)(row0 + 8 - col - 1 + 256) <= 512u;
            s[nt][0] = i00 ? s[nt][0] * 0.125f : -1e30f;
            s[nt][1] = i01 ? s[nt][1] * 0.125f : -1e30f;
            s[nt][2] = i10 ? s[nt][2] * 0.125f : -1e30f;
            s[nt][3] = i11 ? s[nt][3] * 0.125f : -1e30f;
            rmax0 = fmaxf(rmax0, fmaxf(s[nt][0], s[nt][1]));
            rmax1 = fmaxf(rmax1, fmaxf(s[nt][2], s[nt][3]));
        }
        rmax0 = fmaxf(rmax0, __shfl_xor_sync(0xffffffffu, rmax0, 1));
        rmax0 = fmaxf(rmax0, __shfl_xor_sync(0xffffffffu, rmax0, 2));
        rmax1 = fmaxf(rmax1, __shfl_xor_sync(0xffffffffu, rmax1, 1));
        rmax1 = fmaxf(rmax1, __shfl_xor_sync(0xffffffffu, rmax1, 2));

        const float nm0 = fmaxf(m0, rmax0);
        const float nm1 = fmaxf(m1, rmax1);
        const float c0 = __expf(m0 - nm0);
        const float c1 = __expf(m1 - nm1);
        m0 = nm0; m1 = nm1;

        float add0 = 0.f, add1 = 0.f;
        uint32_t p[16][2];
#pragma unroll
        for (int nt = 0; nt < 16; nt++) {
            const float p00 = __expf(s[nt][0] - nm0);
            const float p01 = __expf(s[nt][1] - nm0);
            const float p10 = __expf(s[nt][2] - nm1);
            const float p11 = __expf(s[nt][3] - nm1);
            add0 += p00 + p01;
            add1 += p10 + p11;
            p[nt][0] = packbf(p00, p01);
            p[nt][1] = packbf(p10, p11);
        }
        add0 += __shfl_xor_sync(0xffffffffu, add0, 1);
        add0 += __shfl_xor_sync(0xffffffffu, add0, 2);
        add1 += __shfl_xor_sync(0xffffffffu, add1, 1);
        add1 += __shfl_xor_sync(0xffffffffu, add1, 2);
        l0 = l0 * c0 + add0;
        l1 = l1 * c1 + add1;
#pragma unroll
        for (int nd = 0; nd < 8; nd++) {
            o[nd][0] *= c0; o[nd][1] *= c0;
            o[nd][2] *= c1; o[nd][3] *= c1;
        }

        // O += P · V   (A = P fragments straight from accum layout, B via ldsm.trans)
#pragma unroll
        for (int ks = 0; ks < 8; ks++) {
            uint32_t a[4] = {p[2 * ks][0], p[2 * ks][1], p[2 * ks + 1][0], p[2 * ks + 1][1]};
#pragma unroll
            for (int nd = 0; nd < 8; nd++) {
                uint32_t bv[2];
                const uint32_t ro = (uint32_t)(ks * 16 + vrow) * ATT_RSB + nd * 16;
                ldsm_x2t(bv[0], bv[1], pV + ro);
                mma_bf16(o[nd], a, bv);
            }
        }
        __syncthreads();
    }

    // epilogue: o /= l, write bf16 hi/lo
    const float inv0 = 1.f / l0;
    const float inv1 = 1.f / l1;
#pragma unroll
    for (int nd = 0; nd < 8; nd++) {
        const int d = nd * 8 + tq * 2;
        const size_t o0 = (size_t)(b * S_ + row0) * D_ + h * 64 + d;
        const size_t o1 = (size_t)(b * S_ + row0 + 8) * D_ + h * 64 + d;
        const float v00 = o[nd][0] * inv0, v01 = o[nd][1] * inv0;
        const float v10 = o[nd][2] * inv1, v11 = o[nd][3] * inv1;
        uint32_t h0 = packbf(v00, v01);
        uint32_t h1 = packbf(v10, v11);
        __nv_bfloat162 hb0 = *(__nv_bfloat162*)&h0;
        __nv_bfloat162 hb1 = *(__nv_bfloat162*)&h1;
        *(uint32_t*)(Oh + o0) = h0;
        *(uint32_t*)(Oh + o1) = h1;
        *(uint32_t*)(Ol + o0) = packbf(v00 - __bfloat162float(hb0.x),
                                       v01 - __bfloat162float(hb0.y));
        *(uint32_t*)(Ol + o1) = packbf(v10 - __bfloat162float(hb1.x),
                                       v11 - __bfloat162float(hb1.y));
    }
}

// ---------------------------------------------------------------------------
// Fused residual add + LayerNorm; writes x fp32 and xh/xl bf16
// ---------------------------------------------------------------------------
__global__ __launch_bounds__(256) void add_ln_kernel(
    float* __restrict__ x, const float* __restrict__ r,
    const float* __restrict__ g, const float* __restrict__ be,
    __nv_bfloat16* __restrict__ xh, __nv_bfloat16* __restrict__ xl)
{
    const int row = blockIdx.x;
    const int tid = threadIdx.x;
    float* xp = x + (size_t)row * D_;
    const float* rp = r + (size_t)row * D_;

    float v[3];
    float s1 = 0.f, s2 = 0.f;
#pragma unroll
    for (int i = 0; i < 3; i++) {
        const int c = tid + 256 * i;
        v[i] = xp[c] + rp[c];
        s1 += v[i];
        s2 += v[i] * v[i];
    }
#pragma unroll
    for (int off = 16; off; off >>= 1) {
        s1 += __shfl_xor_sync(0xffffffffu, s1, off);
        s2 += __shfl_xor_sync(0xffffffffu, s2, off);
    }
    __shared__ float r1[8], r2[8];
    if ((tid & 31) == 0) { r1[tid >> 5] = s1; r2[tid >> 5] = s2; }
    __syncthreads();
    s1 = 0.f; s2 = 0.f;
#pragma unroll
    for (int i = 0; i < 8; i++) { s1 += r1[i]; s2 += r2[i]; }

    const float mean = s1 * (1.f / 768.f);
    const float var  = s2 * (1.f / 768.f) - mean * mean;
    const float rstd = rsqrtf(var + 1e-5f);
#pragma unroll
    for (int i = 0; i < 3; i++) {
        const int c = tid + 256 * i;
        const float val = (v[i] - mean) * rstd * g[c] + be[c];
        xp[c] = val;
        const __nv_bfloat16 hb = __float2bfloat16(val);
        xh[(size_t)row * D_ + c] = hb;
        xl[(size_t)row * D_ + c] = __float2bfloat16(val - __bfloat162float(hb));
    }
}

// ---------------------------------------------------------------------------
// Host orchestration
// ---------------------------------------------------------------------------
static void run_split(const float* in, __nv_bfloat16* hi, __nv_bfloat16* lo, int n)
{
    int n4 = n >> 2;
    split_kernel<<<(n4 + 255) / 256, 256>>>(in, hi, lo, n4);
}

template <int EPI>
static void run_gemm(const __nv_bfloat16* Ah, const __nv_bfloat16* Al,
                     const __nv_bfloat16* Wh, const __nv_bfloat16* Wl,
                     const float* bias, float* C,
                     __nv_bfloat16* Hi, __nv_bfloat16* Lo, int M, int N, int K)
{
    dim3 grid(N / 128, M / 128);
    gemm_mma_kernel<EPI><<<grid, 256, GEMM_SMEM>>>(Ah, Al, Wh, Wl, bias, C, Hi, Lo, M, N, K);
}

extern "C" void kernel_launch(void* const* d_in, const int* in_sizes, int n_in,
                              void* d_out, int out_size)
{
    const float* src = (const float*)d_in[0];
    const float* qw  = (const float*)d_in[1];
    const float* qb  = (const float*)d_in[2];
    const float* kw  = (const float*)d_in[3];
    const float* kb  = (const float*)d_in[4];
    const float* vw  = (const float*)d_in[5];
    const float* vb  = (const float*)d_in[6];
    const float* ow  = (const float*)d_in[7];
    const float* ob  = (const float*)d_in[8];
    const float* w1  = (const float*)d_in[9];
    const float* b1  = (const float*)d_in[10];
    const float* w2  = (const float*)d_in[11];
    const float* b2  = (const float*)d_in[12];
    const float* g1  = (const float*)d_in[13];
    const float* be1 = (const float*)d_in[14];
    const float* g2  = (const float*)d_in[15];
    const float* be2 = (const float*)d_in[16];

    cudaFuncSetAttribute(gemm_mma_kernel<0>, cudaFuncAttributeMaxDynamicSharedMemorySize, GEMM_SMEM);
    cudaFuncSetAttribute(gemm_mma_kernel<1>, cudaFuncAttributeMaxDynamicSharedMemorySize, GEMM_SMEM);
    cudaFuncSetAttribute(gemm_mma_kernel<2>, cudaFuncAttributeMaxDynamicSharedMemorySize, GEMM_SMEM);
    cudaFuncSetAttribute(gemm_mma_kernel<3>, cudaFuncAttributeMaxDynamicSharedMemorySize, GEMM_SMEM);
    cudaFuncSetAttribute(attn_mma_kernel, cudaFuncAttributeMaxDynamicSharedMemorySize, ATT_SMEM);

    float *x, *tmp;
    __nv_bfloat16 *xh, *xl, *qh, *ql, *kh, *kl, *vh, *oh, *ol, *ffh, *ffl, *wh, *wl;
    cudaGetSymbolAddress((void**)&x,   g_x);
    cudaGetSymbolAddress((void**)&tmp, g_tmp);
    cudaGetSymbolAddress((void**)&xh,  g_xh);
    cudaGetSymbolAddress((void**)&xl,  g_xl);
    cudaGetSymbolAddress((void**)&qh,  g_qh);
    cudaGetSymbolAddress((void**)&ql,  g_ql);
    cudaGetSymbolAddress((void**)&kh,  g_kh);
    cudaGetSymbolAddress((void**)&kl,  g_kl);
    cudaGetSymbolAddress((void**)&vh,  g_vh);
    cudaGetSymbolAddress((void**)&oh,  g_oh);
    cudaGetSymbolAddress((void**)&ol,  g_ol);
    cudaGetSymbolAddress((void**)&ffh, g_ffh);
    cudaGetSymbolAddress((void**)&ffl, g_ffl);
    cudaGetSymbolAddress((void**)&wh,  g_wh);
    cudaGetSymbolAddress((void**)&wl,  g_wl);

    const size_t xbytes = (size_t)MROWS * D_ * sizeof(float);
    cudaMemcpyAsync(x, src, xbytes, cudaMemcpyDeviceToDevice, 0);
    run_split(src, xh, xl, MROWS * D_);

    for (int l = 0; l < L_; l++) {
        const float* qwl = qw + (size_t)l * D_ * D_;
        const float* kwl = kw + (size_t)l * D_ * D_;
        const float* vwl = vw + (size_t)l * D_ * D_;
        const float* owl = ow + (size_t)l * D_ * D_;
        const float* w1l = w1 + (size_t)l * DFF_ * D_;
        const float* w2l = w2 + (size_t)l * D_ * DFF_;

        // projections: q,k split outputs; v hi-only
        run_split(qwl, wh, wl, D_ * D_);
        run_gemm<1>(xh, xl, wh, wl, qb + l * D_, nullptr, qh, ql, MROWS, D_, D_);
        run_split(kwl, wh, wl, D_ * D_);
        run_gemm<1>(xh, xl, wh, wl, kb + l * D_, nullptr, kh, kl, MROWS, D_, D_);
        run_split(vwl, wh, wl, D_ * D_);
        run_gemm<3>(xh, xl, wh, wl, vb + l * D_, nullptr, vh, nullptr, MROWS, D_, D_);

        // banded attention (tensor core)
        {
            dim3 grid(S_ / 128, H_, B_);
            attn_mma_kernel<<<grid, 256, ATT_SMEM>>>(qh, ql, kh, kl, vh, oh, ol);
        }

        // output projection (fp32) + residual LN (emits xh/xl)
        run_split(owl, wh, wl, D_ * D_);
        run_gemm<0>(oh, ol, wh, wl, ob + l * D_, tmp, nullptr, nullptr, MROWS, D_, D_);
        add_ln_kernel<<<MROWS, 256>>>(x, tmp, g1 + l * D_, be1 + l * D_, xh, xl);

        // FFN
        run_split(w1l, wh, wl, DFF_ * D_);
        run_gemm<2>(xh, xl, wh, wl, b1 + l * DFF_, nullptr, ffh, ffl, MROWS, DFF_, D_);
        run_split(w2l, wh, wl, D_ * DFF_);
        run_gemm<0>(ffh, ffl, wh, wl, b2 + l * D_, tmp, nullptr, nullptr, MROWS, D_, DFF_);
        add_ln_kernel<<<MROWS, 256>>>(x, tmp, g2 + l * D_, be2 + l * D_, xh, xl);
    }

    cudaMemcpyAsync(d_out, x, xbytes, cudaMemcpyDeviceToDevice, 0);
}

// round 5
// speedup vs baseline: 2.9625x; 1.0878x over previous
#include <cuda_runtime.h>
#include <cuda_bf16.h>
#include <cstdint>

// Problem constants
#define B_ 2
#define S_ 2048
#define D_ 768
#define H_ 12
#define DH_ 64
#define L_ 2
#define DFF_ 3072
#define MROWS (B_ * S_)   // 4096
#define NQKV 2304

// ---------------------------------------------------------------------------
// Scratch (static device globals — no allocation allowed)
// ---------------------------------------------------------------------------
__device__ float g_x  [MROWS * D_];
__device__ float g_tmp[MROWS * D_];
__device__ float g_bqkv[NQKV];
__device__ __nv_bfloat16 g_xh[MROWS * D_];
__device__ __nv_bfloat16 g_xl[MROWS * D_];
__device__ __nv_bfloat16 g_oh[MROWS * D_];
__device__ __nv_bfloat16 g_ol[MROWS * D_];
__device__ __nv_bfloat16 g_ffh[MROWS * DFF_];   // also holds packed QKV (M x 2304)
__device__ __nv_bfloat16 g_ffl[MROWS * DFF_];
__device__ __nv_bfloat16 g_wh[DFF_ * D_];
__device__ __nv_bfloat16 g_wl[DFF_ * D_];

// ---------------------------------------------------------------------------
// Baseline-PTX tensor-core helpers
// ---------------------------------------------------------------------------
__device__ __forceinline__ uint32_t smem_u32(const void* p) {
    uint32_t a;
    asm("{ .reg .u64 t; cvta.to.shared.u64 t, %1; cvt.u32.u64 %0, t; }"
        : "=r"(a) : "l"(p));
    return a;
}
__device__ __forceinline__ void ldsm_x4(uint32_t& r0, uint32_t& r1,
                                        uint32_t& r2, uint32_t& r3, uint32_t a) {
    asm volatile("ldmatrix.sync.aligned.m8n8.x4.shared.b16 {%0,%1,%2,%3}, [%4];"
                 : "=r"(r0), "=r"(r1), "=r"(r2), "=r"(r3) : "r"(a));
}
__device__ __forceinline__ void ldsm_x2(uint32_t& r0, uint32_t& r1, uint32_t a) {
    asm volatile("ldmatrix.sync.aligned.m8n8.x2.shared.b16 {%0,%1}, [%2];"
                 : "=r"(r0), "=r"(r1) : "r"(a));
}
__device__ __forceinline__ void ldsm_x2t(uint32_t& r0, uint32_t& r1, uint32_t a) {
    asm volatile("ldmatrix.sync.aligned.m8n8.x2.trans.shared.b16 {%0,%1}, [%2];"
                 : "=r"(r0), "=r"(r1) : "r"(a));
}
__device__ __forceinline__ void mma_bf16(float* d, const uint32_t* a, const uint32_t* b) {
    asm volatile(
        "mma.sync.aligned.m16n8k16.row.col.f32.bf16.bf16.f32 "
        "{%0,%1,%2,%3}, {%4,%5,%6,%7}, {%8,%9}, {%0,%1,%2,%3};"
        : "+f"(d[0]), "+f"(d[1]), "+f"(d[2]), "+f"(d[3])
        : "r"(a[0]), "r"(a[1]), "r"(a[2]), "r"(a[3]), "r"(b[0]), "r"(b[1]));
}
#define CP16(dst, src) \
    asm volatile("cp.async.cg.shared.global [%0], [%1], 16;" :: "r"(dst), "l"(src))
#define CP_COMMIT() asm volatile("cp.async.commit_group;" ::: "memory")
#define CP_WAIT1()  asm volatile("cp.async.wait_group 1;" ::: "memory")
#define CP_WAIT0()  asm volatile("cp.async.wait_group 0;" ::: "memory")

__device__ __forceinline__ uint32_t packbf(float a, float b) {
    __nv_bfloat162 t = __floats2bfloat162_rn(a, b);
    return *(uint32_t*)&t;
}

// ---------------------------------------------------------------------------
// Split fp32 -> bf16 hi + bf16 lo
// ---------------------------------------------------------------------------
__global__ __launch_bounds__(256) void split_kernel(
    const float* __restrict__ in, __nv_bfloat16* __restrict__ hi,
    __nv_bfloat16* __restrict__ lo, int n4)
{
    int i = blockIdx.x * blockDim.x + threadIdx.x;
    if (i >= n4) return;
    float4 x = ((const float4*)in)[i];
    __nv_bfloat16 h0 = __float2bfloat16(x.x), h1 = __float2bfloat16(x.y);
    __nv_bfloat16 h2 = __float2bfloat16(x.z), h3 = __float2bfloat16(x.w);
    __nv_bfloat16 l0 = __float2bfloat16(x.x - __bfloat162float(h0));
    __nv_bfloat16 l1 = __float2bfloat16(x.y - __bfloat162float(h1));
    __nv_bfloat16 l2 = __float2bfloat16(x.z - __bfloat162float(h2));
    __nv_bfloat16 l3 = __float2bfloat16(x.w - __bfloat162float(h3));
    __nv_bfloat162* hp = (__nv_bfloat162*)hi;
    __nv_bfloat162* lp = (__nv_bfloat162*)lo;
    hp[2 * i + 0] = __nv_bfloat162(h0, h1);
    hp[2 * i + 1] = __nv_bfloat162(h2, h3);
    lp[2 * i + 0] = __nv_bfloat162(l0, l1);
    lp[2 * i + 1] = __nv_bfloat162(l2, l3);
}

// ---------------------------------------------------------------------------
// mma.sync split-bf16 GEMM: 128x128 CTA tile, BK=32, 8 warps, warp 64x32.
// 3-stage cp.async pipeline, single syncthreads per chunk.
// EPI: 0 = fp32 C (+bias); 1 = split hi/lo (+bias); 2 = relu + split hi/lo
// ---------------------------------------------------------------------------
#define RS_B 80              // smem row stride bytes (40 bf16)
#define TILE_B (128 * RS_B)
#define STAGE_B (4 * TILE_B)
#define GEMM_SMEM (3 * STAGE_B)  // 122880

template <int EPI>
__global__ __launch_bounds__(256) void gemm_mma_kernel(
    const __nv_bfloat16* __restrict__ Ah, const __nv_bfloat16* __restrict__ Al,
    const __nv_bfloat16* __restrict__ Wh, const __nv_bfloat16* __restrict__ Wl,
    const float* __restrict__ bias, float* __restrict__ C,
    __nv_bfloat16* __restrict__ Hi, __nv_bfloat16* __restrict__ Lo,
    int M, int N, int K)
{
    extern __shared__ char smem[];
    const uint32_t sb = smem_u32(smem);

    const int tid = threadIdx.x;
    const int wid = tid >> 5;
    const int lane = tid & 31;
    const int warp_m = wid >> 2;
    const int warp_n = wid & 3;
    const int bm = blockIdx.y * 128;
    const int bn = blockIdx.x * 128;

    float acc[4][4][4];
#pragma unroll
    for (int mi = 0; mi < 4; mi++)
#pragma unroll
        for (int ni = 0; ni < 4; ni++)
#pragma unroll
            for (int r = 0; r < 4; r++) acc[mi][ni][r] = 0.f;

    const int i0 = tid, i1 = tid + 256;
    const int lr0 = i0 >> 2, ls0 = i0 & 3;
    const int lr1 = i1 >> 2, ls1 = i1 & 3;

    auto load_chunk = [&](int kc, int stage) {
        const uint32_t base = sb + stage * STAGE_B;
        const size_t a0 = (size_t)(bm + lr0) * K + kc + ls0 * 8;
        const size_t a1 = (size_t)(bm + lr1) * K + kc + ls1 * 8;
        const size_t b0 = (size_t)(bn + lr0) * K + kc + ls0 * 8;
        const size_t b1 = (size_t)(bn + lr1) * K + kc + ls1 * 8;
        const uint32_t d0 = lr0 * RS_B + ls0 * 16;
        const uint32_t d1 = lr1 * RS_B + ls1 * 16;
        CP16(base + d0,              Ah + a0);
        CP16(base + d1,              Ah + a1);
        CP16(base + TILE_B + d0,     Al + a0);
        CP16(base + TILE_B + d1,     Al + a1);
        CP16(base + 2 * TILE_B + d0, Wh + b0);
        CP16(base + 2 * TILE_B + d1, Wh + b1);
        CP16(base + 3 * TILE_B + d0, Wl + b0);
        CP16(base + 3 * TILE_B + d1, Wl + b1);
    };

    const int arow = warp_m * 64 + (lane & 15);
    const int akb  = (lane >> 4) * 8;
    const int brow = warp_n * 32 + (lane & 7);
    const int bkb  = ((lane >> 3) & 1) * 8;

    auto compute = [&](int stage) {
        const uint32_t base = sb + stage * STAGE_B;
        const uint32_t pAh = base;
        const uint32_t pAl = base + TILE_B;
        const uint32_t pBh = base + 2 * TILE_B;
        const uint32_t pBl = base + 3 * TILE_B;
#pragma unroll
        for (int ks = 0; ks < 2; ks++) {
            const int k0 = ks * 16;
            uint32_t ah[4][4], al[4][4], bh[4][2], bl[4][2];
#pragma unroll
            for (int mi = 0; mi < 4; mi++) {
                const uint32_t ro = (uint32_t)(arow + mi * 16) * RS_B + (k0 + akb) * 2;
                ldsm_x4(ah[mi][0], ah[mi][1], ah[mi][2], ah[mi][3], pAh + ro);
                ldsm_x4(al[mi][0], al[mi][1], al[mi][2], al[mi][3], pAl + ro);
            }
#pragma unroll
            for (int ni = 0; ni < 4; ni++) {
                const uint32_t ro = (uint32_t)(brow + ni * 8) * RS_B + (k0 + bkb) * 2;
                ldsm_x2(bh[ni][0], bh[ni][1], pBh + ro);
                ldsm_x2(bl[ni][0], bl[ni][1], pBl + ro);
            }
#pragma unroll
            for (int mi = 0; mi < 4; mi++)
#pragma unroll
                for (int ni = 0; ni < 4; ni++) {
                    mma_bf16(acc[mi][ni], ah[mi], bh[ni]);
                    mma_bf16(acc[mi][ni], ah[mi], bl[ni]);
                    mma_bf16(acc[mi][ni], al[mi], bh[ni]);
                }
        }
    };

    const int nchunks = K >> 5;
    load_chunk(0, 0);
    CP_COMMIT();
    if (nchunks > 1) { load_chunk(32, 1); CP_COMMIT(); }

    int stage = 0;
    for (int c = 0; c < nchunks; c++) {
        if (c + 1 < nchunks) { CP_WAIT1(); } else { CP_WAIT0(); }
        __syncthreads();
        if (c + 2 < nchunks) {
            int s2 = stage + 2; if (s2 >= 3) s2 -= 3;
            load_chunk((c + 2) << 5, s2);
            CP_COMMIT();
        }
        compute(stage);
        if (++stage == 3) stage = 0;
    }

    // epilogue
#pragma unroll
    for (int mi = 0; mi < 4; mi++) {
        const int m0 = bm + warp_m * 64 + mi * 16 + (lane >> 2);
#pragma unroll
        for (int ni = 0; ni < 4; ni++) {
            const int n0 = bn + warp_n * 32 + ni * 8 + (lane & 3) * 2;
            const float bx = bias[n0], by = bias[n0 + 1];
            float v00 = acc[mi][ni][0] + bx, v01 = acc[mi][ni][1] + by;
            float v10 = acc[mi][ni][2] + bx, v11 = acc[mi][ni][3] + by;
            if (EPI == 2) {
                v00 = fmaxf(v00, 0.f); v01 = fmaxf(v01, 0.f);
                v10 = fmaxf(v10, 0.f); v11 = fmaxf(v11, 0.f);
            }
            if (EPI == 0) {
                *(float2*)(C + (size_t)m0 * N + n0) = make_float2(v00, v01);
                *(float2*)(C + (size_t)(m0 + 8) * N + n0) = make_float2(v10, v11);
            } else {
                uint32_t h0 = packbf(v00, v01);
                uint32_t h1 = packbf(v10, v11);
                __nv_bfloat162 hb0 = *(__nv_bfloat162*)&h0;
                __nv_bfloat162 hb1 = *(__nv_bfloat162*)&h1;
                uint32_t l0 = packbf(v00 - __bfloat162float(hb0.x),
                                     v01 - __bfloat162float(hb0.y));
                uint32_t l1 = packbf(v10 - __bfloat162float(hb1.x),
                                     v11 - __bfloat162float(hb1.y));
                *(uint32_t*)(Hi + (size_t)m0 * N + n0) = h0;
                *(uint32_t*)(Hi + (size_t)(m0 + 8) * N + n0) = h1;
                *(uint32_t*)(Lo + (size_t)m0 * N + n0) = l0;
                *(uint32_t*)(Lo + (size_t)(m0 + 8) * N + n0) = l1;
            }
        }
    }
}

// ---------------------------------------------------------------------------
// Tensor-core banded flash attention (reads packed QKV with stride ldq).
// ---------------------------------------------------------------------------
#define ATT_RSB 144                 // row stride bytes (72 bf16, 64 used)
#define ATT_TILE_B (128 * ATT_RSB)  // 18432
#define ATT_SMEM (8 * ATT_TILE_B)   // Qh,Ql + 2 stages x (Kh,Kl,V) = 147456

__global__ __launch_bounds__(256) void attn_mma_kernel(
    const __nv_bfloat16* __restrict__ Qh, const __nv_bfloat16* __restrict__ Ql,
    const __nv_bfloat16* __restrict__ Kh, const __nv_bfloat16* __restrict__ Kl,
    const __nv_bfloat16* __restrict__ Vh, int ldq,
    __nv_bfloat16* __restrict__ Oh, __nv_bfloat16* __restrict__ Ol)
{
    extern __shared__ char smem[];
    const uint32_t sb = smem_u32(smem);
    const int b = blockIdx.z;
    const int h = blockIdx.y;
    const int qt = blockIdx.x;
    const int q0 = qt * 128;
    const int tid = threadIdx.x;
    const int wid = tid >> 5;
    const int lane = tid & 31;
    const int g = lane >> 2;
    const int tq = lane & 3;

    const uint32_t sQh = sb;
    const uint32_t sQl = sb + ATT_TILE_B;
    const uint32_t sKV0 = sb + 2 * ATT_TILE_B;

    {
        const int row = tid >> 3, seg = tid & 7;
#pragma unroll
        for (int t = 0; t < 4; t++) {
            const int r = row + t * 32;
            const size_t go = (size_t)(b * S_ + q0 + r) * ldq + h * 64 + seg * 8;
            const uint32_t so = (uint32_t)r * ATT_RSB + seg * 16;
            CP16(sQh + so, Qh + go);
            CP16(sQl + so, Ql + go);
        }
    }
    CP_COMMIT();

    const int kt_lo = (qt - 2 < 0) ? 0 : qt - 2;
    const int kt_hi = (qt + 2 > S_ / 128 - 1) ? S_ / 128 - 1 : qt + 2;

    auto load_kv = [&](int kt, int stg) {
        const uint32_t base = sKV0 + stg * 3 * ATT_TILE_B;
        const int row = tid >> 3, seg = tid & 7;
#pragma unroll
        for (int t = 0; t < 4; t++) {
            const int r = row + t * 32;
            const size_t go = (size_t)(b * S_ + kt * 128 + r) * ldq + h * 64 + seg * 8;
            const uint32_t so = (uint32_t)r * ATT_RSB + seg * 16;
            CP16(base + so,                  Kh + go);
            CP16(base + ATT_TILE_B + so,     Kl + go);
            CP16(base + 2 * ATT_TILE_B + so, Vh + go);
        }
    };
    load_kv(kt_lo, 0);
    CP_COMMIT();

    CP_WAIT1();
    __syncthreads();

    uint32_t qhf[4][4], qlf[4][4];
    {
        const int arow = wid * 16 + (lane & 15);
        const int akb = (lane >> 4) * 8;
#pragma unroll
        for (int ks = 0; ks < 4; ks++) {
            const uint32_t ro = (uint32_t)arow * ATT_RSB + (ks * 16 + akb) * 2;
            ldsm_x4(qhf[ks][0], qhf[ks][1], qhf[ks][2], qhf[ks][3], sQh + ro);
            ldsm_x4(qlf[ks][0], qlf[ks][1], qlf[ks][2], qlf[ks][3], sQl + ro);
        }
    }

    float m0 = -1e30f, m1 = -1e30f, l0 = 0.f, l1 = 0.f;
    float o[8][4];
#pragma unroll
    for (int nd = 0; nd < 8; nd++)
#pragma unroll
        for (int r = 0; r < 4; r++) o[nd][r] = 0.f;

    const int row0 = q0 + wid * 16 + g;
    const int brow0 = lane & 7;
    const int bkb = ((lane >> 3) & 1) * 8;
    const int vrow = lane & 15;

    for (int kt = kt_lo; kt <= kt_hi; kt++) {
        const int i = kt - kt_lo;
        const int stg = i & 1;
        if (kt < kt_hi) {
            load_kv(kt + 1, stg ^ 1);
            CP_COMMIT();
            CP_WAIT1();
        } else {
            CP_WAIT0();
        }
        __syncthreads();

        const uint32_t base = sKV0 + stg * 3 * ATT_TILE_B;
        const uint32_t pKh = base, pKl = base + ATT_TILE_B, pV = base + 2 * ATT_TILE_B;

        float s[16][4];
#pragma unroll
        for (int nt = 0; nt < 16; nt++)
#pragma unroll
            for (int r = 0; r < 4; r++) s[nt][r] = 0.f;
#pragma unroll
        for (int ks = 0; ks < 4; ks++) {
#pragma unroll
            for (int nt = 0; nt < 16; nt++) {
                uint32_t bh[2], bl[2];
                const uint32_t ro = (uint32_t)(nt * 8 + brow0) * ATT_RSB + (ks * 16 + bkb) * 2;
                ldsm_x2(bh[0], bh[1], pKh + ro);
                ldsm_x2(bl[0], bl[1], pKl + ro);
                mma_bf16(s[nt], qhf[ks], bh);
                mma_bf16(s[nt], qhf[ks], bl);
                mma_bf16(s[nt], qlf[ks], bh);
            }
        }

        float rmax0 = -1e30f, rmax1 = -1e30f;
#pragma unroll
        for (int nt = 0; nt < 16; nt++) {
            const int col = kt * 128 + nt * 8 + tq * 2;
            const bool i00 = (unsigned)(row0 - col + 256) <= 512u;
            const bool i01 = (unsigned)(row0 - col - 1 + 256) <= 512u;
            const bool i10 = (unsigned)(row0 + 8 - col + 256) <= 512u;
            const bool i11 = (unsigned)(row0 + 8 - col - 1 + 256) <= 512u;
            s[nt][0] = i00 ? s[nt][0] * 0.125f : -1e30f;
            s[nt][1] = i01 ? s[nt][1] * 0.125f : -1e30f;
            s[nt][2] = i10 ? s[nt][2] * 0.125f : -1e30f;
            s[nt][3] = i11 ? s[nt][3] * 0.125f : -1e30f;
            rmax0 = fmaxf(rmax0, fmaxf(s[nt][0], s[nt][1]));
            rmax1 = fmaxf(rmax1, fmaxf(s[nt][2], s[nt][3]));
        }
        rmax0 = fmaxf(rmax0, __shfl_xor_sync(0xffffffffu, rmax0, 1));
        rmax0 = fmaxf(rmax0, __shfl_xor_sync(0xffffffffu, rmax0, 2));
        rmax1 = fmaxf(rmax1, __shfl_xor_sync(0xffffffffu, rmax1, 1));
        rmax1 = fmaxf(rmax1, __shfl_xor_sync(0xffffffffu, rmax1, 2));

        const float nm0 = fmaxf(m0, rmax0);
        const float nm1 = fmaxf(m1, rmax1);
        const float c0 = __expf(m0 - nm0);
        const float c1 = __expf(m1 - nm1);
        m0 = nm0; m1 = nm1;

        float add0 = 0.f, add1 = 0.f;
        uint32_t p[16][2];
#pragma unroll
        for (int nt = 0; nt < 16; nt++) {
            const float p00 = __expf(s[nt][0] - nm0);
            const float p01 = __expf(s[nt][1] - nm0);
            const float p10 = __expf(s[nt][2] - nm1);
            const float p11 = __expf(s[nt][3] - nm1);
            add0 += p00 + p01;
            add1 += p10 + p11;
            p[nt][0] = packbf(p00, p01);
            p[nt][1] = packbf(p10, p11);
        }
        add0 += __shfl_xor_sync(0xffffffffu, add0, 1);
        add0 += __shfl_xor_sync(0xffffffffu, add0, 2);
        add1 += __shfl_xor_sync(0xffffffffu, add1, 1);
        add1 += __shfl_xor_sync(0xffffffffu, add1, 2);
        l0 = l0 * c0 + add0;
        l1 = l1 * c1 + add1;
#pragma unroll
        for (int nd = 0; nd < 8; nd++) {
            o[nd][0] *= c0; o[nd][1] *= c0;
            o[nd][2] *= c1; o[nd][3] *= c1;
        }

#pragma unroll
        for (int ks = 0; ks < 8; ks++) {
            uint32_t a[4] = {p[2 * ks][0], p[2 * ks][1], p[2 * ks + 1][0], p[2 * ks + 1][1]};
#pragma unroll
            for (int nd = 0; nd < 8; nd++) {
                uint32_t bv[2];
                const uint32_t ro = (uint32_t)(ks * 16 + vrow) * ATT_RSB + nd * 16;
                ldsm_x2t(bv[0], bv[1], pV + ro);
                mma_bf16(o[nd], a, bv);
            }
        }
        __syncthreads();
    }

    const float inv0 = 1.f / l0;
    const float inv1 = 1.f / l1;
#pragma unroll
    for (int nd = 0; nd < 8; nd++) {
        const int d = nd * 8 + tq * 2;
        const size_t o0 = (size_t)(b * S_ + row0) * D_ + h * 64 + d;
        const size_t o1 = (size_t)(b * S_ + row0 + 8) * D_ + h * 64 + d;
        const float v00 = o[nd][0] * inv0, v01 = o[nd][1] * inv0;
        const float v10 = o[nd][2] * inv1, v11 = o[nd][3] * inv1;
        uint32_t h0 = packbf(v00, v01);
        uint32_t h1 = packbf(v10, v11);
        __nv_bfloat162 hb0 = *(__nv_bfloat162*)&h0;
        __nv_bfloat162 hb1 = *(__nv_bfloat162*)&h1;
        *(uint32_t*)(Oh + o0) = h0;
        *(uint32_t*)(Oh + o1) = h1;
        *(uint32_t*)(Ol + o0) = packbf(v00 - __bfloat162float(hb0.x),
                                       v01 - __bfloat162float(hb0.y));
        *(uint32_t*)(Ol + o1) = packbf(v10 - __bfloat162float(hb1.x),
                                       v11 - __bfloat162float(hb1.y));
    }
}

// ---------------------------------------------------------------------------
// Fused residual add + LayerNorm; writes x fp32 and xh/xl bf16
// ---------------------------------------------------------------------------
__global__ __launch_bounds__(256) void add_ln_kernel(
    float* __restrict__ x, const float* __restrict__ r,
    const float* __restrict__ g, const float* __restrict__ be,
    __nv_bfloat16* __restrict__ xh, __nv_bfloat16* __restrict__ xl)
{
    const int row = blockIdx.x;
    const int tid = threadIdx.x;
    float* xp = x + (size_t)row * D_;
    const float* rp = r + (size_t)row * D_;

    float v[3];
    float s1 = 0.f, s2 = 0.f;
#pragma unroll
    for (int i = 0; i < 3; i++) {
        const int c = tid + 256 * i;
        v[i] = xp[c] + rp[c];
        s1 += v[i];
        s2 += v[i] * v[i];
    }
#pragma unroll
    for (int off = 16; off; off >>= 1) {
        s1 += __shfl_xor_sync(0xffffffffu, s1, off);
        s2 += __shfl_xor_sync(0xffffffffu, s2, off);
    }
    __shared__ float r1[8], r2[8];
    if ((tid & 31) == 0) { r1[tid >> 5] = s1; r2[tid >> 5] = s2; }
    __syncthreads();
    s1 = 0.f; s2 = 0.f;
#pragma unroll
    for (int i = 0; i < 8; i++) { s1 += r1[i]; s2 += r2[i]; }

    const float mean = s1 * (1.f / 768.f);
    const float var  = s2 * (1.f / 768.f) - mean * mean;
    const float rstd = rsqrtf(var + 1e-5f);
#pragma unroll
    for (int i = 0; i < 3; i++) {
        const int c = tid + 256 * i;
        const float val = (v[i] - mean) * rstd * g[c] + be[c];
        xp[c] = val;
        const __nv_bfloat16 hb = __float2bfloat16(val);
        xh[(size_t)row * D_ + c] = hb;
        xl[(size_t)row * D_ + c] = __float2bfloat16(val - __bfloat162float(hb));
    }
}

// ---------------------------------------------------------------------------
// Host orchestration
// ---------------------------------------------------------------------------
static void run_split(const float* in, __nv_bfloat16* hi, __nv_bfloat16* lo, int n)
{
    int n4 = n >> 2;
    split_kernel<<<(n4 + 255) / 256, 256>>>(in, hi, lo, n4);
}

template <int EPI>
static void run_gemm(const __nv_bfloat16* Ah, const __nv_bfloat16* Al,
                     const __nv_bfloat16* Wh, const __nv_bfloat16* Wl,
                     const float* bias, float* C,
                     __nv_bfloat16* Hi, __nv_bfloat16* Lo, int M, int N, int K)
{
    dim3 grid(N / 128, M / 128);
    gemm_mma_kernel<EPI><<<grid, 256, GEMM_SMEM>>>(Ah, Al, Wh, Wl, bias, C, Hi, Lo, M, N, K);
}

extern "C" void kernel_launch(void* const* d_in, const int* in_sizes, int n_in,
                              void* d_out, int out_size)
{
    const float* src = (const float*)d_in[0];
    const float* qw  = (const float*)d_in[1];
    const float* qb  = (const float*)d_in[2];
    const float* kw  = (const float*)d_in[3];
    const float* kb  = (const float*)d_in[4];
    const float* vw  = (const float*)d_in[5];
    const float* vb  = (const float*)d_in[6];
    const float* ow  = (const float*)d_in[7];
    const float* ob  = (const float*)d_in[8];
    const float* w1  = (const float*)d_in[9];
    const float* b1  = (const float*)d_in[10];
    const float* w2  = (const float*)d_in[11];
    const float* b2  = (const float*)d_in[12];
    const float* g1  = (const float*)d_in[13];
    const float* be1 = (const float*)d_in[14];
    const float* g2  = (const float*)d_in[15];
    const float* be2 = (const float*)d_in[16];

    cudaFuncSetAttribute(gemm_mma_kernel<0>, cudaFuncAttributeMaxDynamicSharedMemorySize, GEMM_SMEM);
    cudaFuncSetAttribute(gemm_mma_kernel<1>, cudaFuncAttributeMaxDynamicSharedMemorySize, GEMM_SMEM);
    cudaFuncSetAttribute(gemm_mma_kernel<2>, cudaFuncAttributeMaxDynamicSharedMemorySize, GEMM_SMEM);
    cudaFuncSetAttribute(attn_mma_kernel, cudaFuncAttributeMaxDynamicSharedMemorySize, ATT_SMEM);

    float *x, *tmp, *bqkv;
    __nv_bfloat16 *xh, *xl, *oh, *ol, *ffh, *ffl, *wh, *wl;
    cudaGetSymbolAddress((void**)&x,    g_x);
    cudaGetSymbolAddress((void**)&tmp,  g_tmp);
    cudaGetSymbolAddress((void**)&bqkv, g_bqkv);
    cudaGetSymbolAddress((void**)&xh,   g_xh);
    cudaGetSymbolAddress((void**)&xl,   g_xl);
    cudaGetSymbolAddress((void**)&oh,   g_oh);
    cudaGetSymbolAddress((void**)&ol,   g_ol);
    cudaGetSymbolAddress((void**)&ffh,  g_ffh);
    cudaGetSymbolAddress((void**)&ffl,  g_ffl);
    cudaGetSymbolAddress((void**)&wh,   g_wh);
    cudaGetSymbolAddress((void**)&wl,   g_wl);

    const size_t xbytes = (size_t)MROWS * D_ * sizeof(float);
    cudaMemcpyAsync(x, src, xbytes, cudaMemcpyDeviceToDevice, 0);
    run_split(src, xh, xl, MROWS * D_);

    for (int l = 0; l < L_; l++) {
        const float* qwl = qw + (size_t)l * D_ * D_;
        const float* kwl = kw + (size_t)l * D_ * D_;
        const float* vwl = vw + (size_t)l * D_ * D_;
        const float* owl = ow + (size_t)l * D_ * D_;
        const float* w1l = w1 + (size_t)l * DFF_ * D_;
        const float* w2l = w2 + (size_t)l * D_ * DFF_;

        // fused QKV projection: W = [qw; kw; vw]  (2304 x 768)
        run_split(qwl, wh,               wl,               D_ * D_);
        run_split(kwl, wh + D_ * D_,     wl + D_ * D_,     D_ * D_);
        run_split(vwl, wh + 2 * D_ * D_, wl + 2 * D_ * D_, D_ * D_);
        cudaMemcpyAsync(bqkv,          qb + l * D_, D_ * sizeof(float), cudaMemcpyDeviceToDevice, 0);
        cudaMemcpyAsync(bqkv + D_,     kb + l * D_, D_ * sizeof(float), cudaMemcpyDeviceToDevice, 0);
        cudaMemcpyAsync(bqkv + 2 * D_, vb + l * D_, D_ * sizeof(float), cudaMemcpyDeviceToDevice, 0);
        run_gemm<1>(xh, xl, wh, wl, bqkv, nullptr, ffh, ffl, MROWS, NQKV, D_);

        // banded attention on packed QKV
        {
            dim3 grid(S_ / 128, H_, B_);
            attn_mma_kernel<<<grid, 256, ATT_SMEM>>>(
                ffh, ffl, ffh + D_, ffl + D_, ffh + 2 * D_, NQKV, oh, ol);
        }

        // output projection (fp32) + residual LN (emits xh/xl)
        run_split(owl, wh, wl, D_ * D_);
        run_gemm<0>(oh, ol, wh, wl, ob + l * D_, tmp, nullptr, nullptr, MROWS, D_, D_);
        add_ln_kernel<<<MROWS, 256>>>(x, tmp, g1 + l * D_, be1 + l * D_, xh, xl);

        // FFN
        run_split(w1l, wh, wl, DFF_ * D_);
        run_gemm<2>(xh, xl, wh, wl, b1 + l * DFF_, nullptr, ffh, ffl, MROWS, DFF_, D_);
        run_split(w2l, wh, wl, D_ * DFF_);
        run_gemm<0>(ffh, ffl, wh, wl, b2 + l * D_, tmp, nullptr, nullptr, MROWS, D_, DFF_);
        add_ln_kernel<<<MROWS, 256>>>(x, tmp, g2 + l * D_, be2 + l * D_, xh, xl);
    }

    cudaMemcpyAsync(d_out, x, xbytes, cudaMemcpyDeviceToDevice, 0);
}

// round 6
// speedup vs baseline: 6.9625x; 2.3502x over previous
#include <cuda_runtime.h>
#include <cuda_bf16.h>
#include <cuda_fp16.h>
#include <cstdint>

// Problem constants
#define B_ 2
#define S_ 2048
#define D_ 768
#define H_ 12
#define DH_ 64
#define L_ 2
#define DFF_ 3072
#define MROWS (B_ * S_)   // 4096
#define NQKV 2304

// ---------------------------------------------------------------------------
// Scratch (static device globals — no allocation allowed)
// ---------------------------------------------------------------------------
__device__ float g_x  [MROWS * D_];
__device__ float g_tmp[MROWS * D_];
__device__ float g_bqkv[NQKV];
__device__ __half g_xf [MROWS * D_];
__device__ __half g_of [MROWS * D_];
__device__ __half g_fff[MROWS * DFF_];   // also holds packed QKV (M x 2304)
__device__ __half g_wf [DFF_ * D_];

// ---------------------------------------------------------------------------
// Baseline-PTX tensor-core helpers
// ---------------------------------------------------------------------------
__device__ __forceinline__ uint32_t smem_u32(const void* p) {
    uint32_t a;
    asm("{ .reg .u64 t; cvta.to.shared.u64 t, %1; cvt.u32.u64 %0, t; }"
        : "=r"(a) : "l"(p));
    return a;
}
__device__ __forceinline__ void ldsm_x4(uint32_t& r0, uint32_t& r1,
                                        uint32_t& r2, uint32_t& r3, uint32_t a) {
    asm volatile("ldmatrix.sync.aligned.m8n8.x4.shared.b16 {%0,%1,%2,%3}, [%4];"
                 : "=r"(r0), "=r"(r1), "=r"(r2), "=r"(r3) : "r"(a));
}
__device__ __forceinline__ void ldsm_x2(uint32_t& r0, uint32_t& r1, uint32_t a) {
    asm volatile("ldmatrix.sync.aligned.m8n8.x2.shared.b16 {%0,%1}, [%2];"
                 : "=r"(r0), "=r"(r1) : "r"(a));
}
__device__ __forceinline__ void ldsm_x2t(uint32_t& r0, uint32_t& r1, uint32_t a) {
    asm volatile("ldmatrix.sync.aligned.m8n8.x2.trans.shared.b16 {%0,%1}, [%2];"
                 : "=r"(r0), "=r"(r1) : "r"(a));
}
__device__ __forceinline__ void mma_f16(float* d, const uint32_t* a, const uint32_t* b) {
    asm volatile(
        "mma.sync.aligned.m16n8k16.row.col.f32.f16.f16.f32 "
        "{%0,%1,%2,%3}, {%4,%5,%6,%7}, {%8,%9}, {%0,%1,%2,%3};"
        : "+f"(d[0]), "+f"(d[1]), "+f"(d[2]), "+f"(d[3])
        : "r"(a[0]), "r"(a[1]), "r"(a[2]), "r"(a[3]), "r"(b[0]), "r"(b[1]));
}
#define CP16(dst, src) \
    asm volatile("cp.async.cg.shared.global [%0], [%1], 16;" :: "r"(dst), "l"(src))
#define CP_COMMIT() asm volatile("cp.async.commit_group;" ::: "memory")
#define CP_WAIT0()  asm volatile("cp.async.wait_group 0;" ::: "memory")
#define CP_WAIT1()  asm volatile("cp.async.wait_group 1;" ::: "memory")
#define CP_WAIT2()  asm volatile("cp.async.wait_group 2;" ::: "memory")

__device__ __forceinline__ uint32_t packh(float a, float b) {
    __half2 t = __floats2half2_rn(a, b);
    return *(uint32_t*)&t;
}

// ---------------------------------------------------------------------------
// Convert fp32 -> fp16
// ---------------------------------------------------------------------------
__global__ __launch_bounds__(256) void cvt_kernel(
    const float* __restrict__ in, __half* __restrict__ out, int n4)
{
    int i = blockIdx.x * blockDim.x + threadIdx.x;
    if (i >= n4) return;
    float4 x = ((const float4*)in)[i];
    __half2* op = (__half2*)out;
    op[2 * i + 0] = __floats2half2_rn(x.x, x.y);
    op[2 * i + 1] = __floats2half2_rn(x.z, x.w);
}

// ---------------------------------------------------------------------------
// fp16 mma.sync GEMM: C[M,N] = A[M,K] @ W[N,K]^T + bias
// 128x128 CTA tile, BK=32, 8 warps (2x4), warp tile 64x32.
// 4-stage cp.async pipeline, single syncthreads per chunk.
// EPI: 0 = fp32 C (+bias); 1 = fp16 out (+bias); 2 = relu + fp16 out
// ---------------------------------------------------------------------------
#define RS_B 80              // smem row stride bytes (40 halves, 32 used)
#define TILE_B (128 * RS_B)  // 10240
#define STAGE_B (2 * TILE_B) // A + W
#define NSTAGE 4
#define GEMM_SMEM (NSTAGE * STAGE_B)  // 81920

template <int EPI>
__global__ __launch_bounds__(256) void gemm_mma_kernel(
    const __half* __restrict__ A, const __half* __restrict__ W,
    const float* __restrict__ bias, float* __restrict__ C,
    __half* __restrict__ Hf, int M, int N, int K)
{
    extern __shared__ char smem[];
    const uint32_t sb = smem_u32(smem);

    const int tid = threadIdx.x;
    const int wid = tid >> 5;
    const int lane = tid & 31;
    const int warp_m = wid >> 2;
    const int warp_n = wid & 3;
    const int bm = blockIdx.y * 128;
    const int bn = blockIdx.x * 128;

    float acc[4][4][4];
#pragma unroll
    for (int mi = 0; mi < 4; mi++)
#pragma unroll
        for (int ni = 0; ni < 4; ni++)
#pragma unroll
            for (int r = 0; r < 4; r++) acc[mi][ni][r] = 0.f;

    const int lr0 = tid >> 2,        ls0 = tid & 3;
    const int lr1 = (tid + 256) >> 2, ls1 = (tid + 256) & 3;

    auto load_chunk = [&](int kc, int stage) {
        const uint32_t base = sb + stage * STAGE_B;
        const size_t a0 = (size_t)(bm + lr0) * K + kc + ls0 * 8;
        const size_t a1 = (size_t)(bm + lr1) * K + kc + ls1 * 8;
        const size_t b0 = (size_t)(bn + lr0) * K + kc + ls0 * 8;
        const size_t b1 = (size_t)(bn + lr1) * K + kc + ls1 * 8;
        const uint32_t d0 = lr0 * RS_B + ls0 * 16;
        const uint32_t d1 = lr1 * RS_B + ls1 * 16;
        CP16(base + d0,          A + a0);
        CP16(base + d1,          A + a1);
        CP16(base + TILE_B + d0, W + b0);
        CP16(base + TILE_B + d1, W + b1);
    };

    // A frags: standard m16 lane mapping
    const int arow = warp_m * 64 + (lane & 15);
    const int akb  = (lane >> 4) * 8;
    // B frags via x4: group g = lane>>3; ni_off = g>>1; khalf = g&1
    const int bg_ni = (lane >> 4);         // 0 or 1  -> ni2 + bg_ni
    const int bg_kh = ((lane >> 3) & 1) * 8;
    const int brow_l = lane & 7;

    auto compute = [&](int stage) {
        const uint32_t base = sb + stage * STAGE_B;
        const uint32_t pA = base;
        const uint32_t pB = base + TILE_B;
#pragma unroll
        for (int ks = 0; ks < 2; ks++) {
            const int k0 = ks * 16;
            uint32_t af[4][4], bf[4][2];
#pragma unroll
            for (int mi = 0; mi < 4; mi++) {
                const uint32_t ro = (uint32_t)(arow + mi * 16) * RS_B + (k0 + akb) * 2;
                ldsm_x4(af[mi][0], af[mi][1], af[mi][2], af[mi][3], pA + ro);
            }
#pragma unroll
            for (int np = 0; np < 2; np++) {    // ni pairs {0,1}, {2,3}
                const int nrow = warp_n * 32 + (np * 2 + bg_ni) * 8 + brow_l;
                const uint32_t ro = (uint32_t)nrow * RS_B + (k0 + bg_kh) * 2;
                ldsm_x4(bf[np * 2][0], bf[np * 2][1], bf[np * 2 + 1][0], bf[np * 2 + 1][1], pB + ro);
            }
#pragma unroll
            for (int mi = 0; mi < 4; mi++)
#pragma unroll
                for (int ni = 0; ni < 4; ni++)
                    mma_f16(acc[mi][ni], af[mi], bf[ni]);
        }
    };

    const int nchunks = K >> 5;
    load_chunk(0, 0);
    CP_COMMIT();
    if (nchunks > 1) { load_chunk(32, 1); CP_COMMIT(); }
    if (nchunks > 2) { load_chunk(64, 2); CP_COMMIT(); }

    for (int c = 0; c < nchunks; c++) {
        const int rem = nchunks - 1 - c;
        if (rem >= 2) { CP_WAIT2(); }
        else if (rem == 1) { CP_WAIT1(); }
        else { CP_WAIT0(); }
        __syncthreads();
        if (c + 3 < nchunks) {
            int s3 = (c + 3) & (NSTAGE - 1);
            load_chunk((c + 3) << 5, s3);
            CP_COMMIT();
        }
        compute(c & (NSTAGE - 1));
    }

    // epilogue
#pragma unroll
    for (int mi = 0; mi < 4; mi++) {
        const int m0 = bm + warp_m * 64 + mi * 16 + (lane >> 2);
#pragma unroll
        for (int ni = 0; ni < 4; ni++) {
            const int n0 = bn + warp_n * 32 + ni * 8 + (lane & 3) * 2;
            const float bx = bias[n0], by = bias[n0 + 1];
            float v00 = acc[mi][ni][0] + bx, v01 = acc[mi][ni][1] + by;
            float v10 = acc[mi][ni][2] + bx, v11 = acc[mi][ni][3] + by;
            if (EPI == 2) {
                v00 = fmaxf(v00, 0.f); v01 = fmaxf(v01, 0.f);
                v10 = fmaxf(v10, 0.f); v11 = fmaxf(v11, 0.f);
            }
            if (EPI == 0) {
                *(float2*)(C + (size_t)m0 * N + n0) = make_float2(v00, v01);
                *(float2*)(C + (size_t)(m0 + 8) * N + n0) = make_float2(v10, v11);
            } else {
                *(uint32_t*)(Hf + (size_t)m0 * N + n0) = packh(v00, v01);
                *(uint32_t*)(Hf + (size_t)(m0 + 8) * N + n0) = packh(v10, v11);
            }
        }
    }
}

// ---------------------------------------------------------------------------
// Tensor-core banded flash attention, fp16 single-product.
// CTA = (qtile of 128, head, batch); 8 warps x 16 q-rows.
// K-tiles of 128 keys double-buffered. Band: |i-j| <= 256. Emits fp16 O.
// ---------------------------------------------------------------------------
#define ATT_RSB 144
#define ATT_TILE_B (128 * ATT_RSB)        // 18432
#define ATT_SMEM (5 * ATT_TILE_B)         // Q + 2 stages x (K,V) = 92160

__global__ __launch_bounds__(256) void attn_mma_kernel(
    const __half* __restrict__ Qf, const __half* __restrict__ Kf,
    const __half* __restrict__ Vf, int ldq, __half* __restrict__ Of)
{
    extern __shared__ char smem[];
    const uint32_t sb = smem_u32(smem);
    const int b = blockIdx.z;
    const int h = blockIdx.y;
    const int qt = blockIdx.x;
    const int q0 = qt * 128;
    const int tid = threadIdx.x;
    const int wid = tid >> 5;
    const int lane = tid & 31;
    const int g = lane >> 2;
    const int tq = lane & 3;

    const uint32_t sQ = sb;
    const uint32_t sKV0 = sb + ATT_TILE_B;   // stage s at sKV0 + s*2*ATT_TILE_B

    {
        const int row = tid >> 1, seg = tid & 1;
#pragma unroll
        for (int t = 0; t < 4; t++) {
            const size_t go = (size_t)(b * S_ + q0 + row) * ldq + h * 64 + (seg * 4 + t) * 8;
            CP16(sQ + (uint32_t)row * ATT_RSB + (seg * 4 + t) * 16, Qf + go);
        }
    }
    CP_COMMIT();

    const int kt_lo = (qt - 2 < 0) ? 0 : qt - 2;
    const int kt_hi = (qt + 2 > S_ / 128 - 1) ? S_ / 128 - 1 : qt + 2;

    auto load_kv = [&](int kt, int stg) {
        const uint32_t base = sKV0 + stg * 2 * ATT_TILE_B;
        const int row = tid >> 1, seg = tid & 1;
#pragma unroll
        for (int t = 0; t < 4; t++) {
            const size_t go = (size_t)(b * S_ + kt * 128 + row) * ldq + h * 64 + (seg * 4 + t) * 8;
            const uint32_t so = (uint32_t)row * ATT_RSB + (seg * 4 + t) * 16;
            CP16(base + so,              Kf + go);
            CP16(base + ATT_TILE_B + so, Vf + go);
        }
    };
    load_kv(kt_lo, 0);
    CP_COMMIT();

    CP_WAIT1();
    __syncthreads();

    uint32_t qf[4][4];
    {
        const int arow = wid * 16 + (lane & 15);
        const int akb = (lane >> 4) * 8;
#pragma unroll
        for (int ks = 0; ks < 4; ks++) {
            const uint32_t ro = (uint32_t)arow * ATT_RSB + (ks * 16 + akb) * 2;
            ldsm_x4(qf[ks][0], qf[ks][1], qf[ks][2], qf[ks][3], sQ + ro);
        }
    }

    float m0 = -1e30f, m1 = -1e30f, l0 = 0.f, l1 = 0.f;
    float o[8][4];
#pragma unroll
    for (int nd = 0; nd < 8; nd++)
#pragma unroll
        for (int r = 0; r < 4; r++) o[nd][r] = 0.f;

    const int row0 = q0 + wid * 16 + g;
    const int brow0 = lane & 7;
    const int bkb = ((lane >> 3) & 1) * 8;
    const int vrow = lane & 15;

    for (int kt = kt_lo; kt <= kt_hi; kt++) {
        const int stg = (kt - kt_lo) & 1;
        if (kt < kt_hi) {
            load_kv(kt + 1, stg ^ 1);
            CP_COMMIT();
            CP_WAIT1();
        } else {
            CP_WAIT0();
        }
        __syncthreads();

        const uint32_t base = sKV0 + stg * 2 * ATT_TILE_B;
        const uint32_t pK = base, pV = base + ATT_TILE_B;

        float s[16][4];
#pragma unroll
        for (int nt = 0; nt < 16; nt++)
#pragma unroll
            for (int r = 0; r < 4; r++) s[nt][r] = 0.f;
#pragma unroll
        for (int ks = 0; ks < 4; ks++) {
#pragma unroll
            for (int nt = 0; nt < 16; nt++) {
                uint32_t bk[2];
                const uint32_t ro = (uint32_t)(nt * 8 + brow0) * ATT_RSB + (ks * 16 + bkb) * 2;
                ldsm_x2(bk[0], bk[1], pK + ro);
                mma_f16(s[nt], qf[ks], bk);
            }
        }

        float rmax0 = -1e30f, rmax1 = -1e30f;
#pragma unroll
        for (int nt = 0; nt < 16; nt++) {
            const int col = kt * 128 + nt * 8 + tq * 2;
            const bool i00 = (unsigned)(row0 - col + 256) <= 512u;
            const bool i01 = (unsigned)(row0 - col - 1 + 256) <= 512u;
            const bool i10 = (unsigned)(row0 + 8 - col + 256) <= 512u;
            const bool i11 = (unsigned)(row0 + 8 - col - 1 + 256) <= 512u;
            s[nt][0] = i00 ? s[nt][0] * 0.125f : -1e30f;
            s[nt][1] = i01 ? s[nt][1] * 0.125f : -1e30f;
            s[nt][2] = i10 ? s[nt][2] * 0.125f : -1e30f;
            s[nt][3] = i11 ? s[nt][3] * 0.125f : -1e30f;
            rmax0 = fmaxf(rmax0, fmaxf(s[nt][0], s[nt][1]));
            rmax1 = fmaxf(rmax1, fmaxf(s[nt][2], s[nt][3]));
        }
        rmax0 = fmaxf(rmax0, __shfl_xor_sync(0xffffffffu, rmax0, 1));
        rmax0 = fmaxf(rmax0, __shfl_xor_sync(0xffffffffu, rmax0, 2));
        rmax1 = fmaxf(rmax1, __shfl_xor_sync(0xffffffffu, rmax1, 1));
        rmax1 = fmaxf(rmax1, __shfl_xor_sync(0xffffffffu, rmax1, 2));

        const float nm0 = fmaxf(m0, rmax0);
        const float nm1 = fmaxf(m1, rmax1);
        const float c0 = __expf(m0 - nm0);
        const float c1 = __expf(m1 - nm1);
        m0 = nm0; m1 = nm1;

        float add0 = 0.f, add1 = 0.f;
        uint32_t p[16][2];
#pragma unroll
        for (int nt = 0; nt < 16; nt++) {
            const float p00 = __expf(s[nt][0] - nm0);
            const float p01 = __expf(s[nt][1] - nm0);
            const float p10 = __expf(s[nt][2] - nm1);
            const float p11 = __expf(s[nt][3] - nm1);
            add0 += p00 + p01;
            add1 += p10 + p11;
            p[nt][0] = packh(p00, p01);
            p[nt][1] = packh(p10, p11);
        }
        add0 += __shfl_xor_sync(0xffffffffu, add0, 1);
        add0 += __shfl_xor_sync(0xffffffffu, add0, 2);
        add1 += __shfl_xor_sync(0xffffffffu, add1, 1);
        add1 += __shfl_xor_sync(0xffffffffu, add1, 2);
        l0 = l0 * c0 + add0;
        l1 = l1 * c1 + add1;
#pragma unroll
        for (int nd = 0; nd < 8; nd++) {
            o[nd][0] *= c0; o[nd][1] *= c0;
            o[nd][2] *= c1; o[nd][3] *= c1;
        }

#pragma unroll
        for (int ks = 0; ks < 8; ks++) {
            uint32_t a[4] = {p[2 * ks][0], p[2 * ks][1], p[2 * ks + 1][0], p[2 * ks + 1][1]};
#pragma unroll
            for (int nd = 0; nd < 8; nd++) {
                uint32_t bv[2];
                const uint32_t ro = (uint32_t)(ks * 16 + vrow) * ATT_RSB + nd * 16;
                ldsm_x2t(bv[0], bv[1], pV + ro);
                mma_f16(o[nd], a, bv);
            }
        }
        __syncthreads();
    }

    const float inv0 = 1.f / l0;
    const float inv1 = 1.f / l1;
#pragma unroll
    for (int nd = 0; nd < 8; nd++) {
        const int d = nd * 8 + tq * 2;
        const size_t o0 = (size_t)(b * S_ + row0) * D_ + h * 64 + d;
        const size_t o1 = (size_t)(b * S_ + row0 + 8) * D_ + h * 64 + d;
        *(uint32_t*)(Of + o0) = packh(o[nd][0] * inv0, o[nd][1] * inv0);
        *(uint32_t*)(Of + o1) = packh(o[nd][2] * inv1, o[nd][3] * inv1);
    }
}

// ---------------------------------------------------------------------------
// Fused residual add + LayerNorm; writes x fp32 and xf fp16
// ---------------------------------------------------------------------------
__global__ __launch_bounds__(256) void add_ln_kernel(
    float* __restrict__ x, const float* __restrict__ r,
    const float* __restrict__ g, const float* __restrict__ be,
    __half* __restrict__ xf)
{
    const int row = blockIdx.x;
    const int tid = threadIdx.x;
    float* xp = x + (size_t)row * D_;
    const float* rp = r + (size_t)row * D_;

    float v[3];
    float s1 = 0.f, s2 = 0.f;
#pragma unroll
    for (int i = 0; i < 3; i++) {
        const int c = tid + 256 * i;
        v[i] = xp[c] + rp[c];
        s1 += v[i];
        s2 += v[i] * v[i];
    }
#pragma unroll
    for (int off = 16; off; off >>= 1) {
        s1 += __shfl_xor_sync(0xffffffffu, s1, off);
        s2 += __shfl_xor_sync(0xffffffffu, s2, off);
    }
    __shared__ float r1[8], r2[8];
    if ((tid & 31) == 0) { r1[tid >> 5] = s1; r2[tid >> 5] = s2; }
    __syncthreads();
    s1 = 0.f; s2 = 0.f;
#pragma unroll
    for (int i = 0; i < 8; i++) { s1 += r1[i]; s2 += r2[i]; }

    const float mean = s1 * (1.f / 768.f);
    const float var  = s2 * (1.f / 768.f) - mean * mean;
    const float rstd = rsqrtf(var + 1e-5f);
#pragma unroll
    for (int i = 0; i < 3; i++) {
        const int c = tid + 256 * i;
        const float val = (v[i] - mean) * rstd * g[c] + be[c];
        xp[c] = val;
        xf[(size_t)row * D_ + c] = __float2half_rn(val);
    }
}

// ---------------------------------------------------------------------------
// Host orchestration
// ---------------------------------------------------------------------------
static void run_cvt(const float* in, __half* out, int n)
{
    int n4 = n >> 2;
    cvt_kernel<<<(n4 + 255) / 256, 256>>>(in, out, n4);
}

template <int EPI>
static void run_gemm(const __half* A, const __half* W, const float* bias,
                     float* C, __half* Hf, int M, int N, int K)
{
    dim3 grid(N / 128, M / 128);
    gemm_mma_kernel<EPI><<<grid, 256, GEMM_SMEM>>>(A, W, bias, C, Hf, M, N, K);
}

extern "C" void kernel_launch(void* const* d_in, const int* in_sizes, int n_in,
                              void* d_out, int out_size)
{
    const float* src = (const float*)d_in[0];
    const float* qw  = (const float*)d_in[1];
    const float* qb  = (const float*)d_in[2];
    const float* kw  = (const float*)d_in[3];
    const float* kb  = (const float*)d_in[4];
    const float* vw  = (const float*)d_in[5];
    const float* vb  = (const float*)d_in[6];
    const float* ow  = (const float*)d_in[7];
    const float* ob  = (const float*)d_in[8];
    const float* w1  = (const float*)d_in[9];
    const float* b1  = (const float*)d_in[10];
    const float* w2  = (const float*)d_in[11];
    const float* b2  = (const float*)d_in[12];
    const float* g1  = (const float*)d_in[13];
    const float* be1 = (const float*)d_in[14];
    const float* g2  = (const float*)d_in[15];
    const float* be2 = (const float*)d_in[16];

    cudaFuncSetAttribute(gemm_mma_kernel<0>, cudaFuncAttributeMaxDynamicSharedMemorySize, GEMM_SMEM);
    cudaFuncSetAttribute(gemm_mma_kernel<1>, cudaFuncAttributeMaxDynamicSharedMemorySize, GEMM_SMEM);
    cudaFuncSetAttribute(gemm_mma_kernel<2>, cudaFuncAttributeMaxDynamicSharedMemorySize, GEMM_SMEM);
    cudaFuncSetAttribute(attn_mma_kernel, cudaFuncAttributeMaxDynamicSharedMemorySize, ATT_SMEM);

    float *x, *tmp, *bqkv;
    __half *xf, *of, *fff, *wf;
    cudaGetSymbolAddress((void**)&x,    g_x);
    cudaGetSymbolAddress((void**)&tmp,  g_tmp);
    cudaGetSymbolAddress((void**)&bqkv, g_bqkv);
    cudaGetSymbolAddress((void**)&xf,   g_xf);
    cudaGetSymbolAddress((void**)&of,   g_of);
    cudaGetSymbolAddress((void**)&fff,  g_fff);
    cudaGetSymbolAddress((void**)&wf,   g_wf);

    const size_t xbytes = (size_t)MROWS * D_ * sizeof(float);
    cudaMemcpyAsync(x, src, xbytes, cudaMemcpyDeviceToDevice, 0);
    run_cvt(src, xf, MROWS * D_);

    for (int l = 0; l < L_; l++) {
        const float* qwl = qw + (size_t)l * D_ * D_;
        const float* kwl = kw + (size_t)l * D_ * D_;
        const float* vwl = vw + (size_t)l * D_ * D_;
        const float* owl = ow + (size_t)l * D_ * D_;
        const float* w1l = w1 + (size_t)l * DFF_ * D_;
        const float* w2l = w2 + (size_t)l * D_ * DFF_;

        // fused QKV projection: W = [qw; kw; vw]  (2304 x 768)
        run_cvt(qwl, wf,               D_ * D_);
        run_cvt(kwl, wf + D_ * D_,     D_ * D_);
        run_cvt(vwl, wf + 2 * D_ * D_, D_ * D_);
        cudaMemcpyAsync(bqkv,          qb + l * D_, D_ * sizeof(float), cudaMemcpyDeviceToDevice, 0);
        cudaMemcpyAsync(bqkv + D_,     kb + l * D_, D_ * sizeof(float), cudaMemcpyDeviceToDevice, 0);
        cudaMemcpyAsync(bqkv + 2 * D_, vb + l * D_, D_ * sizeof(float), cudaMemcpyDeviceToDevice, 0);
        run_gemm<1>(xf, wf, bqkv, nullptr, fff, MROWS, NQKV, D_);

        // banded attention on packed QKV
        {
            dim3 grid(S_ / 128, H_, B_);
            attn_mma_kernel<<<grid, 256, ATT_SMEM>>>(
                fff, fff + D_, fff + 2 * D_, NQKV, of);
        }

        // output projection (fp32) + residual LN (emits xf)
        run_cvt(owl, wf, D_ * D_);
        run_gemm<0>(of, wf, ob + l * D_, tmp, nullptr, MROWS, D_, D_);
        add_ln_kernel<<<MROWS, 256>>>(x, tmp, g1 + l * D_, be1 + l * D_, xf);

        // FFN
        run_cvt(w1l, wf, DFF_ * D_);
        run_gemm<2>(xf, wf, b1 + l * DFF_, nullptr, fff, MROWS, DFF_, D_);
        run_cvt(w2l, wf, D_ * DFF_);
        run_gemm<0>(fff, wf, b2 + l * D_, tmp, nullptr, MROWS, D_, DFF_);
        add_ln_kernel<<<MROWS, 256>>>(x, tmp, g2 + l * D_, be2 + l * D_, xf);
    }

    cudaMemcpyAsync(d_out, x, xbytes, cudaMemcpyDeviceToDevice, 0);
}